// round 1
// baseline (speedup 1.0000x reference)
#include <cuda_runtime.h>
#include <math_constants.h>
#include <cstdint>
#include <cstddef>

#define HEADS  16
#define DK     64
#define BLKT   129
#define NBLK   32
#define BATCH  4
#define NTOK   (BLKT * NBLK)        // 4128
#define MROWS  (BATCH * NTOK)       // 16512
#define DMODEL 1024
#define QKVC   3072

// Scratch (allocation-free rule: __device__ globals)
__device__ float g_qkv[(size_t)MROWS * QKVC];   // [m][0:1024)=q, [1024:2048)=k, [2048:3072)=v
__device__ float g_o[(size_t)MROWS * DMODEL];   // attention output, pre-Wo

// ---------------------------------------------------------------------------
// SGEMM (NT): C[m, nc0+j] = sum_k A[m,k] * W[nw0+j, k]  (+bias)
// 128x128 tile, BK=16, 256 threads, 8x8 per thread. Weight selected per
// 1024-column group so QKV runs as one grid.
// ---------------------------------------------------------------------------
__global__ __launch_bounds__(256, 2)
void sgemm_nt(const float* __restrict__ A,
              const float* __restrict__ W0, const float* __restrict__ W1,
              const float* __restrict__ W2, const float* __restrict__ bias,
              float* __restrict__ C, int K, int ldc)
{
    __shared__ float As[16][132];
    __shared__ float Bs[16][132];
    const int tid = threadIdx.x;
    const int tx = tid & 15, ty = tid >> 4;
    const int m0 = blockIdx.x << 7;
    const int nblk = blockIdx.y;
    const float* W = (nblk < 8) ? W0 : (nblk < 16) ? W1 : W2;
    const int nw0 = (nblk & 7) << 7;
    const int nc0 = nblk << 7;

    float acc[8][8];
#pragma unroll
    for (int i = 0; i < 8; ++i)
#pragma unroll
        for (int j = 0; j < 8; ++j) acc[i][j] = 0.f;

    for (int k0 = 0; k0 < K; k0 += 16) {
#pragma unroll
        for (int l = 0; l < 2; ++l) {
            int f = tid + (l << 8);
            int r = f >> 2, c4 = (f & 3) << 2;
            float4 va = *(const float4*)&A[(size_t)(m0 + r) * K + k0 + c4];
            As[c4 + 0][r] = va.x; As[c4 + 1][r] = va.y;
            As[c4 + 2][r] = va.z; As[c4 + 3][r] = va.w;
            float4 vb = *(const float4*)&W[(size_t)(nw0 + r) * K + k0 + c4];
            Bs[c4 + 0][r] = vb.x; Bs[c4 + 1][r] = vb.y;
            Bs[c4 + 2][r] = vb.z; Bs[c4 + 3][r] = vb.w;
        }
        __syncthreads();
#pragma unroll
        for (int kk = 0; kk < 16; ++kk) {
            float4 a0 = *(const float4*)&As[kk][ty << 3];
            float4 a1 = *(const float4*)&As[kk][(ty << 3) + 4];
            float4 b0 = *(const float4*)&Bs[kk][tx << 3];
            float4 b1 = *(const float4*)&Bs[kk][(tx << 3) + 4];
            float av[8] = {a0.x, a0.y, a0.z, a0.w, a1.x, a1.y, a1.z, a1.w};
            float bv[8] = {b0.x, b0.y, b0.z, b0.w, b1.x, b1.y, b1.z, b1.w};
#pragma unroll
            for (int i = 0; i < 8; ++i)
#pragma unroll
                for (int j = 0; j < 8; ++j) acc[i][j] += av[i] * bv[j];
        }
        __syncthreads();
    }

    float bv8[8];
#pragma unroll
    for (int j = 0; j < 8; ++j)
        bv8[j] = bias ? bias[nc0 + (tx << 3) + j] : 0.f;

#pragma unroll
    for (int i = 0; i < 8; ++i) {
        int m = m0 + (ty << 3) + i;
        float4 c0, c1;
        c0.x = acc[i][0] + bv8[0]; c0.y = acc[i][1] + bv8[1];
        c0.z = acc[i][2] + bv8[2]; c0.w = acc[i][3] + bv8[3];
        c1.x = acc[i][4] + bv8[4]; c1.y = acc[i][5] + bv8[5];
        c1.z = acc[i][6] + bv8[6]; c1.w = acc[i][7] + bv8[7];
        *(float4*)&C[(size_t)m * ldc + nc0 + (tx << 3)] = c0;
        *(float4*)&C[(size_t)m * ldc + nc0 + (tx << 3) + 4] = c1;
    }
}

// ---------------------------------------------------------------------------
// Block-local attention: one CTA per (head, block, batch).
// K/V tile in smem (pad 68 floats/row -> conflict-free float4), 8 warps,
// each warp processes 2 query rows per pass (halves K-tile smem traffic).
// ---------------------------------------------------------------------------
__global__ __launch_bounds__(256, 2)
void attn_local()
{
    const int h = blockIdx.x, nb = blockIdx.y, b = blockIdx.z;
    const int tid = threadIdx.x, warp = tid >> 5, lane = tid & 31;
    extern __shared__ float sm[];
    float* Ks = sm;                       // 129*68
    float* Vs = Ks + BLKT * 68;           // 129*68
    float* Qs = Vs + BLKT * 68;           // 8*128 (2 q-rows per warp)
    float* Ps = Qs + 8 * 128;             // 8*264 (2 p-rows per warp)

    const size_t base = ((size_t)(b * NTOK + nb * BLKT)) * QKVC + h * DK;

    for (int f = tid; f < BLKT * 16; f += 256) {
        int r = f >> 4, c4 = (f & 15) << 2;
        *(float4*)&Ks[r * 68 + c4] =
            *(const float4*)&g_qkv[base + 1024 + (size_t)r * QKVC + c4];
        *(float4*)&Vs[r * 68 + c4] =
            *(const float4*)&g_qkv[base + 2048 + (size_t)r * QKVC + c4];
    }
    __syncthreads();

    const float scale = 0.125f;           // 1/sqrt(64)
    const int half = lane >> 4;
    const int dl = (lane & 15) << 2;
    float* Qw = Qs + warp * 128;
    float* Pw = Ps + warp * 264;

    for (int p = warp; p < 65; p += 8) {
        const int r0 = p * 2;
        const bool has1 = (r0 + 1) < BLKT;
        const int r1m = has1 ? r0 + 1 : r0;
        Qw[lane]      = g_qkv[base + (size_t)r0 * QKVC + lane];
        Qw[lane + 32] = g_qkv[base + (size_t)r0 * QKVC + lane + 32];
        Qw[64 + lane]      = g_qkv[base + (size_t)r1m * QKVC + lane];
        Qw[64 + lane + 32] = g_qkv[base + (size_t)r1m * QKVC + lane + 32];
        __syncwarp();

        float s0[5], s1[5];
#pragma unroll
        for (int jj = 0; jj < 5; ++jj) {
            const int j = lane + (jj << 5);
            float a0 = 0.f, a1 = 0.f;
            if (j < BLKT) {
                const float* kr = Ks + j * 68;
#pragma unroll
                for (int d4 = 0; d4 < 16; ++d4) {
                    float4 kk4 = *(const float4*)&kr[d4 << 2];
                    float4 q0  = *(const float4*)&Qw[d4 << 2];
                    float4 q1  = *(const float4*)&Qw[64 + (d4 << 2)];
                    a0 += kk4.x * q0.x + kk4.y * q0.y + kk4.z * q0.z + kk4.w * q0.w;
                    a1 += kk4.x * q1.x + kk4.y * q1.y + kk4.z * q1.z + kk4.w * q1.w;
                }
            }
            s0[jj] = (j < BLKT) ? a0 * scale : -CUDART_INF_F;
            s1[jj] = (j < BLKT) ? a1 * scale : -CUDART_INF_F;
        }

        float m0 = s0[0], m1 = s1[0];
#pragma unroll
        for (int jj = 1; jj < 5; ++jj) { m0 = fmaxf(m0, s0[jj]); m1 = fmaxf(m1, s1[jj]); }
#pragma unroll
        for (int o = 16; o > 0; o >>= 1) {
            m0 = fmaxf(m0, __shfl_xor_sync(0xffffffffu, m0, o));
            m1 = fmaxf(m1, __shfl_xor_sync(0xffffffffu, m1, o));
        }
        float e0[5], e1[5], sum0 = 0.f, sum1 = 0.f;
#pragma unroll
        for (int jj = 0; jj < 5; ++jj) {
            const int j = lane + (jj << 5);
            e0[jj] = (j < BLKT) ? __expf(s0[jj] - m0) : 0.f;
            e1[jj] = (j < BLKT) ? __expf(s1[jj] - m1) : 0.f;
            sum0 += e0[jj]; sum1 += e1[jj];
        }
#pragma unroll
        for (int o = 16; o > 0; o >>= 1) {
            sum0 += __shfl_xor_sync(0xffffffffu, sum0, o);
            sum1 += __shfl_xor_sync(0xffffffffu, sum1, o);
        }
        const float i0 = 1.f / sum0, i1 = 1.f / sum1;
#pragma unroll
        for (int jj = 0; jj < 5; ++jj) {
            const int j = lane + (jj << 5);
            if (j < BLKT) { Pw[j] = e0[jj] * i0; Pw[132 + j] = e1[jj] * i1; }
        }
        __syncwarp();

        // PV: lanes 0-15 own dims [4*(lane&15)..+4) for keys 0..64,
        //     lanes 16-31 same dims for keys 65..128, reduced by shfl_xor(16).
        float4 o0 = {0, 0, 0, 0}, o1 = {0, 0, 0, 0};
        const int kbase = half * 65;
        for (int t = 0; t < 65; ++t) {
            const int key = kbase + t;
            if (key < BLKT) {
                const float p0 = Pw[key], p1 = Pw[132 + key];
                float4 vv = *(const float4*)&Vs[key * 68 + dl];
                o0.x += p0 * vv.x; o0.y += p0 * vv.y; o0.z += p0 * vv.z; o0.w += p0 * vv.w;
                o1.x += p1 * vv.x; o1.y += p1 * vv.y; o1.z += p1 * vv.z; o1.w += p1 * vv.w;
            }
        }
        o0.x += __shfl_xor_sync(0xffffffffu, o0.x, 16);
        o0.y += __shfl_xor_sync(0xffffffffu, o0.y, 16);
        o0.z += __shfl_xor_sync(0xffffffffu, o0.z, 16);
        o0.w += __shfl_xor_sync(0xffffffffu, o0.w, 16);
        o1.x += __shfl_xor_sync(0xffffffffu, o1.x, 16);
        o1.y += __shfl_xor_sync(0xffffffffu, o1.y, 16);
        o1.z += __shfl_xor_sync(0xffffffffu, o1.z, 16);
        o1.w += __shfl_xor_sync(0xffffffffu, o1.w, 16);

        const size_t obase = ((size_t)(b * NTOK + nb * BLKT)) * DMODEL + h * DK;
        if (lane < 16) {
            *(float4*)&g_o[obase + (size_t)r0 * DMODEL + dl] = o0;
            if (has1)
                *(float4*)&g_o[obase + (size_t)(r0 + 1) * DMODEL + dl] = o1;
        }
        __syncwarp();
    }
}

// ---------------------------------------------------------------------------
// Global (block-leader) attention: 32 leader tokens per batch. One CTA per
// (b, h), 32 threads, lane = query index. Adds into g_o at block position 0.
// ---------------------------------------------------------------------------
__global__ void attn_global()
{
    const int b = blockIdx.x >> 4, h = blockIdx.x & 15;
    const int lane = threadIdx.x;   // 32 threads
    __shared__ float kg[32 * 65], vg[32 * 65], qg[32 * 65], pg[32 * 33];

    const size_t rb = ((size_t)(b * NTOK + lane * BLKT)) * QKVC + h * DK;
    for (int d = 0; d < 64; ++d) {
        qg[lane * 65 + d] = g_qkv[rb + d];
        kg[lane * 65 + d] = g_qkv[rb + 1024 + d];
        vg[lane * 65 + d] = g_qkv[rb + 2048 + d];
    }
    __syncwarp();

    for (int kk = 0; kk < 32; ++kk) {
        float a = 0.f;
        for (int d = 0; d < 64; ++d) a += qg[lane * 65 + d] * kg[kk * 65 + d];
        pg[lane * 33 + kk] = a * 0.125f;
    }
    float mx = -CUDART_INF_F;
    for (int kk = 0; kk < 32; ++kk) mx = fmaxf(mx, pg[lane * 33 + kk]);
    float sum = 0.f;
    for (int kk = 0; kk < 32; ++kk) {
        float e = __expf(pg[lane * 33 + kk] - mx);
        pg[lane * 33 + kk] = e;
        sum += e;
    }
    const float inv = 1.f / sum;
    __syncwarp();

    const size_t ob = ((size_t)(b * NTOK + lane * BLKT)) * DMODEL + h * DK;
    for (int d = 0; d < 64; ++d) {
        float acc = 0.f;
        for (int kk = 0; kk < 32; ++kk)
            acc += pg[lane * 33 + kk] * vg[kk * 65 + d];
        g_o[ob + d] += acc * inv;
    }
}

// ---------------------------------------------------------------------------
extern "C" void kernel_launch(void* const* d_in, const int* in_sizes, int n_in,
                              void* d_out, int out_size)
{
    const float* x  = (const float*)d_in[0];
    const float* Wq = (const float*)d_in[1];
    const float* Wk = (const float*)d_in[2];
    const float* Wv = (const float*)d_in[3];
    const float* Wo = (const float*)d_in[4];
    const float* bo = (const float*)d_in[5];
    float* out = (float*)d_out;

    float* qkv = nullptr;
    float* osc = nullptr;
    cudaGetSymbolAddress((void**)&qkv, g_qkv);
    cudaGetSymbolAddress((void**)&osc, g_o);

    // 1) fused QKV projection: C = x @ [Wq;Wk;Wv]^T  -> g_qkv [16512 x 3072]
    sgemm_nt<<<dim3(MROWS / 128, 24), 256>>>(x, Wq, Wk, Wv, nullptr,
                                             qkv, DMODEL, QKVC);

    // 2) block-local attention -> g_o
    const size_t smem = (2 * BLKT * 68 + 8 * 128 + 8 * 264) * sizeof(float);
    cudaFuncSetAttribute(attn_local,
                         cudaFuncAttributeMaxDynamicSharedMemorySize, (int)smem);
    attn_local<<<dim3(HEADS, NBLK, BATCH), 256, smem>>>();

    // 3) global leader attention, adds into g_o at block position 0
    attn_global<<<BATCH * HEADS, 32>>>();

    // 4) output projection + bias: out = g_o @ Wo^T + bo
    sgemm_nt<<<dim3(MROWS / 128, 8), 256>>>(osc, Wo, Wo, Wo, bo,
                                            out, DMODEL, DMODEL);
}

// round 3
// speedup vs baseline: 1.7557x; 1.7557x over previous
#include <cuda_runtime.h>
#include <cuda_bf16.h>
#include <math_constants.h>
#include <cstdint>
#include <cstddef>

#define HEADS  16
#define DK     64
#define BLKT   129
#define NBLK   32
#define BATCH  4
#define NTOK   (BLKT * NBLK)        // 4128
#define MROWS  (BATCH * NTOK)       // 16512
#define DMODEL 1024
#define QKVC   3072
#define WROWS  4096                 // Wq,Wk,Wv,Wo concatenated

// Scratch (allocation-free rule: __device__ globals)
__device__ float g_qkv[(size_t)MROWS * QKVC];   // q|k|v fp32
__device__ float g_o[(size_t)MROWS * DMODEL];   // attention output, pre-Wo
__device__ __nv_bfloat16 g_xh[(size_t)MROWS * DMODEL];
__device__ __nv_bfloat16 g_xl[(size_t)MROWS * DMODEL];
__device__ __nv_bfloat16 g_wh[(size_t)WROWS * DMODEL];
__device__ __nv_bfloat16 g_wl[(size_t)WROWS * DMODEL];
__device__ __nv_bfloat16 g_oh[(size_t)MROWS * DMODEL];
__device__ __nv_bfloat16 g_ol[(size_t)MROWS * DMODEL];

// ---------------------------------------------------------------------------
// fp32 -> (hi, lo) bf16 split.  x ~= hi + lo with ~17-bit mantissa coverage.
// ---------------------------------------------------------------------------
__global__ void split_hilo(const float* __restrict__ in,
                           __nv_bfloat16* __restrict__ hi,
                           __nv_bfloat16* __restrict__ lo, int n)
{
    int i = (blockIdx.x * blockDim.x + threadIdx.x) * 4;
    if (i >= n) return;
    float4 v = *(const float4*)(in + i);
    __nv_bfloat16 h0 = __float2bfloat16(v.x);
    __nv_bfloat16 h1 = __float2bfloat16(v.y);
    __nv_bfloat16 h2 = __float2bfloat16(v.z);
    __nv_bfloat16 h3 = __float2bfloat16(v.w);
    __nv_bfloat16 l0 = __float2bfloat16(v.x - __bfloat162float(h0));
    __nv_bfloat16 l1 = __float2bfloat16(v.y - __bfloat162float(h1));
    __nv_bfloat16 l2 = __float2bfloat16(v.z - __bfloat162float(h2));
    __nv_bfloat16 l3 = __float2bfloat16(v.w - __bfloat162float(h3));
    *(__nv_bfloat162*)(hi + i)     = __nv_bfloat162(h0, h1);
    *(__nv_bfloat162*)(hi + i + 2) = __nv_bfloat162(h2, h3);
    *(__nv_bfloat162*)(lo + i)     = __nv_bfloat162(l0, l1);
    *(__nv_bfloat162*)(lo + i + 2) = __nv_bfloat162(l2, l3);
}

// ---------------------------------------------------------------------------
// bf16x3 tensor-core GEMM (NT): C[m,n] = sum_k A[m,k]*B[n,k] (+bias)
// A = Ah+Al, B = Bh+Bl;  C = Ah*Bh + Ah*Bl + Al*Bh  (lo*lo dropped, ~2^-18)
// CTA 128x128, BK=32, 8 warps of 64x32, mma.m16n8k16, cp.async 2-stage.
// ---------------------------------------------------------------------------
#define STAGE_E 20480          // bf16 elems per stage (4 tiles of 128x40)
#define AOFF_H  0
#define AOFF_L  5120
#define BOFF_H  10240
#define BOFF_L  15360

__device__ __forceinline__ void cpa16(void* dst, const void* src) {
    unsigned d = (unsigned)__cvta_generic_to_shared(dst);
    asm volatile("cp.async.cg.shared.global [%0], [%1], 16;\n" :: "r"(d), "l"(src));
}
__device__ __forceinline__ void cp_commit() {
    asm volatile("cp.async.commit_group;\n");
}
template<int N> __device__ __forceinline__ void cp_wait() {
    asm volatile("cp.async.wait_group %0;\n" :: "n"(N));
}
__device__ __forceinline__ void mma16816(float* c, const uint32_t* a, const uint32_t* b) {
    asm volatile(
        "mma.sync.aligned.m16n8k16.row.col.f32.bf16.bf16.f32 "
        "{%0,%1,%2,%3}, {%4,%5,%6,%7}, {%8,%9}, {%0,%1,%2,%3};\n"
        : "+f"(c[0]), "+f"(c[1]), "+f"(c[2]), "+f"(c[3])
        : "r"(a[0]), "r"(a[1]), "r"(a[2]), "r"(a[3]), "r"(b[0]), "r"(b[1]));
}

__global__ __launch_bounds__(256)
void gemm_bf16x3(const __nv_bfloat16* __restrict__ Ahg,
                 const __nv_bfloat16* __restrict__ Alg,
                 const __nv_bfloat16* __restrict__ Bhg,
                 const __nv_bfloat16* __restrict__ Blg,
                 const float* __restrict__ bias,
                 float* __restrict__ C, int K, int ldc)
{
    extern __shared__ __nv_bfloat16 sm[];
    const int tid = threadIdx.x;
    const int warp = tid >> 5, lane = tid & 31;
    const int warp_m = warp & 1, warp_n = warp >> 1;
    const int g = lane >> 2, t = lane & 3;
    const int m0 = blockIdx.x << 7;
    const int n0 = blockIdx.y << 7;

    float acc[4][4][4];
#pragma unroll
    for (int i = 0; i < 4; ++i)
#pragma unroll
        for (int j = 0; j < 4; ++j)
#pragma unroll
            for (int r = 0; r < 4; ++r) acc[i][j][r] = 0.f;

    const int NIT = K >> 5;

    auto loadStage = [&](int st, int k0) {
        __nv_bfloat16* s = sm + st * STAGE_E;
#pragma unroll
        for (int l = 0; l < 2; ++l) {
            int c = tid * 2 + l;                 // 0..511
            int row = c >> 2, kc = (c & 3) << 3; // 8-elem chunk
            size_t ga = (size_t)(m0 + row) * K + k0 + kc;
            size_t gb = (size_t)(n0 + row) * K + k0 + kc;
            int so = row * 40 + kc;
            cpa16(s + AOFF_H + so, Ahg + ga);
            cpa16(s + AOFF_L + so, Alg + ga);
            cpa16(s + BOFF_H + so, Bhg + gb);
            cpa16(s + BOFF_L + so, Blg + gb);
        }
    };

    auto compute = [&](int st) {
        const __nv_bfloat16* s = sm + st * STAGE_E;
#pragma unroll
        for (int ks = 0; ks < 32; ks += 16) {
            uint32_t ah[4][4], al[4][4], bh[4][2], bl[4][2];
#pragma unroll
            for (int i = 0; i < 4; ++i) {
                int m = warp_m * 64 + i * 16 + g;
                const __nv_bfloat16* p = s + AOFF_H + m * 40 + ks + 2 * t;
                ah[i][0] = *(const uint32_t*)p;
                ah[i][1] = *(const uint32_t*)(p + 8 * 40);
                ah[i][2] = *(const uint32_t*)(p + 8);
                ah[i][3] = *(const uint32_t*)(p + 8 * 40 + 8);
                const __nv_bfloat16* q = s + AOFF_L + m * 40 + ks + 2 * t;
                al[i][0] = *(const uint32_t*)q;
                al[i][1] = *(const uint32_t*)(q + 8 * 40);
                al[i][2] = *(const uint32_t*)(q + 8);
                al[i][3] = *(const uint32_t*)(q + 8 * 40 + 8);
            }
#pragma unroll
            for (int j = 0; j < 4; ++j) {
                int n = warp_n * 32 + j * 8 + g;
                const __nv_bfloat16* p = s + BOFF_H + n * 40 + ks + 2 * t;
                bh[j][0] = *(const uint32_t*)p;
                bh[j][1] = *(const uint32_t*)(p + 8);
                const __nv_bfloat16* q = s + BOFF_L + n * 40 + ks + 2 * t;
                bl[j][0] = *(const uint32_t*)q;
                bl[j][1] = *(const uint32_t*)(q + 8);
            }
#pragma unroll
            for (int i = 0; i < 4; ++i)
#pragma unroll
                for (int j = 0; j < 4; ++j) {
                    mma16816(acc[i][j], ah[i], bh[j]);
                    mma16816(acc[i][j], ah[i], bl[j]);
                    mma16816(acc[i][j], al[i], bh[j]);
                }
        }
    };

    loadStage(0, 0);
    cp_commit();
    for (int it = 0; it < NIT; ++it) {
        if (it + 1 < NIT) { loadStage((it + 1) & 1, (it + 1) << 5); cp_commit(); }
        if (it + 1 < NIT) cp_wait<1>(); else cp_wait<0>();
        __syncthreads();
        compute(it & 1);
        __syncthreads();
    }

#pragma unroll
    for (int i = 0; i < 4; ++i) {
        int row0 = m0 + warp_m * 64 + i * 16 + g;
#pragma unroll
        for (int j = 0; j < 4; ++j) {
            int col = n0 + warp_n * 32 + j * 8 + 2 * t;
            float b0 = bias ? bias[col] : 0.f;
            float b1 = bias ? bias[col + 1] : 0.f;
            float2 v0 = {acc[i][j][0] + b0, acc[i][j][1] + b1};
            float2 v1 = {acc[i][j][2] + b0, acc[i][j][3] + b1};
            *(float2*)&C[(size_t)row0 * ldc + col] = v0;
            *(float2*)&C[(size_t)(row0 + 8) * ldc + col] = v1;
        }
    }
}

// ---------------------------------------------------------------------------
// Block-local attention (unchanged from round 1)
// ---------------------------------------------------------------------------
__global__ __launch_bounds__(256, 2)
void attn_local()
{
    const int h = blockIdx.x, nb = blockIdx.y, b = blockIdx.z;
    const int tid = threadIdx.x, warp = tid >> 5, lane = tid & 31;
    extern __shared__ float smf[];
    float* Ks = smf;
    float* Vs = Ks + BLKT * 68;
    float* Qs = Vs + BLKT * 68;
    float* Ps = Qs + 8 * 128;

    const size_t base = ((size_t)(b * NTOK + nb * BLKT)) * QKVC + h * DK;

    for (int f = tid; f < BLKT * 16; f += 256) {
        int r = f >> 4, c4 = (f & 15) << 2;
        *(float4*)&Ks[r * 68 + c4] =
            *(const float4*)&g_qkv[base + 1024 + (size_t)r * QKVC + c4];
        *(float4*)&Vs[r * 68 + c4] =
            *(const float4*)&g_qkv[base + 2048 + (size_t)r * QKVC + c4];
    }
    __syncthreads();

    const float scale = 0.125f;
    const int half = lane >> 4;
    const int dl = (lane & 15) << 2;
    float* Qw = Qs + warp * 128;
    float* Pw = Ps + warp * 264;

    for (int p = warp; p < 65; p += 8) {
        const int r0 = p * 2;
        const bool has1 = (r0 + 1) < BLKT;
        const int r1m = has1 ? r0 + 1 : r0;
        Qw[lane]      = g_qkv[base + (size_t)r0 * QKVC + lane];
        Qw[lane + 32] = g_qkv[base + (size_t)r0 * QKVC + lane + 32];
        Qw[64 + lane]      = g_qkv[base + (size_t)r1m * QKVC + lane];
        Qw[64 + lane + 32] = g_qkv[base + (size_t)r1m * QKVC + lane + 32];
        __syncwarp();

        float s0[5], s1[5];
#pragma unroll
        for (int jj = 0; jj < 5; ++jj) {
            const int j = lane + (jj << 5);
            float a0 = 0.f, a1 = 0.f;
            if (j < BLKT) {
                const float* kr = Ks + j * 68;
#pragma unroll
                for (int d4 = 0; d4 < 16; ++d4) {
                    float4 kk4 = *(const float4*)&kr[d4 << 2];
                    float4 q0  = *(const float4*)&Qw[d4 << 2];
                    float4 q1  = *(const float4*)&Qw[64 + (d4 << 2)];
                    a0 += kk4.x * q0.x + kk4.y * q0.y + kk4.z * q0.z + kk4.w * q0.w;
                    a1 += kk4.x * q1.x + kk4.y * q1.y + kk4.z * q1.z + kk4.w * q1.w;
                }
            }
            s0[jj] = (j < BLKT) ? a0 * scale : -CUDART_INF_F;
            s1[jj] = (j < BLKT) ? a1 * scale : -CUDART_INF_F;
        }

        float m0 = s0[0], m1 = s1[0];
#pragma unroll
        for (int jj = 1; jj < 5; ++jj) { m0 = fmaxf(m0, s0[jj]); m1 = fmaxf(m1, s1[jj]); }
#pragma unroll
        for (int o = 16; o > 0; o >>= 1) {
            m0 = fmaxf(m0, __shfl_xor_sync(0xffffffffu, m0, o));
            m1 = fmaxf(m1, __shfl_xor_sync(0xffffffffu, m1, o));
        }
        float e0[5], e1[5], sum0 = 0.f, sum1 = 0.f;
#pragma unroll
        for (int jj = 0; jj < 5; ++jj) {
            const int j = lane + (jj << 5);
            e0[jj] = (j < BLKT) ? __expf(s0[jj] - m0) : 0.f;
            e1[jj] = (j < BLKT) ? __expf(s1[jj] - m1) : 0.f;
            sum0 += e0[jj]; sum1 += e1[jj];
        }
#pragma unroll
        for (int o = 16; o > 0; o >>= 1) {
            sum0 += __shfl_xor_sync(0xffffffffu, sum0, o);
            sum1 += __shfl_xor_sync(0xffffffffu, sum1, o);
        }
        const float i0 = 1.f / sum0, i1 = 1.f / sum1;
#pragma unroll
        for (int jj = 0; jj < 5; ++jj) {
            const int j = lane + (jj << 5);
            if (j < BLKT) { Pw[j] = e0[jj] * i0; Pw[132 + j] = e1[jj] * i1; }
        }
        __syncwarp();

        float4 o0 = {0, 0, 0, 0}, o1 = {0, 0, 0, 0};
        const int kbase = half * 65;
        for (int tt = 0; tt < 65; ++tt) {
            const int key = kbase + tt;
            if (key < BLKT) {
                const float p0 = Pw[key], p1 = Pw[132 + key];
                float4 vv = *(const float4*)&Vs[key * 68 + dl];
                o0.x += p0 * vv.x; o0.y += p0 * vv.y; o0.z += p0 * vv.z; o0.w += p0 * vv.w;
                o1.x += p1 * vv.x; o1.y += p1 * vv.y; o1.z += p1 * vv.z; o1.w += p1 * vv.w;
            }
        }
        o0.x += __shfl_xor_sync(0xffffffffu, o0.x, 16);
        o0.y += __shfl_xor_sync(0xffffffffu, o0.y, 16);
        o0.z += __shfl_xor_sync(0xffffffffu, o0.z, 16);
        o0.w += __shfl_xor_sync(0xffffffffu, o0.w, 16);
        o1.x += __shfl_xor_sync(0xffffffffu, o1.x, 16);
        o1.y += __shfl_xor_sync(0xffffffffu, o1.y, 16);
        o1.z += __shfl_xor_sync(0xffffffffu, o1.z, 16);
        o1.w += __shfl_xor_sync(0xffffffffu, o1.w, 16);

        const size_t obase = ((size_t)(b * NTOK + nb * BLKT)) * DMODEL + h * DK;
        if (lane < 16) {
            *(float4*)&g_o[obase + (size_t)r0 * DMODEL + dl] = o0;
            if (has1)
                *(float4*)&g_o[obase + (size_t)(r0 + 1) * DMODEL + dl] = o1;
        }
        __syncwarp();
    }
}

// ---------------------------------------------------------------------------
// Global (block-leader) attention (unchanged)
// ---------------------------------------------------------------------------
__global__ void attn_global()
{
    const int b = blockIdx.x >> 4, h = blockIdx.x & 15;
    const int lane = threadIdx.x;
    __shared__ float kg[32 * 65], vg[32 * 65], qg[32 * 65], pg[32 * 33];

    const size_t rb = ((size_t)(b * NTOK + lane * BLKT)) * QKVC + h * DK;
    for (int d = 0; d < 64; ++d) {
        qg[lane * 65 + d] = g_qkv[rb + d];
        kg[lane * 65 + d] = g_qkv[rb + 1024 + d];
        vg[lane * 65 + d] = g_qkv[rb + 2048 + d];
    }
    __syncwarp();

    for (int kk = 0; kk < 32; ++kk) {
        float a = 0.f;
        for (int d = 0; d < 64; ++d) a += qg[lane * 65 + d] * kg[kk * 65 + d];
        pg[lane * 33 + kk] = a * 0.125f;
    }
    float mx = -CUDART_INF_F;
    for (int kk = 0; kk < 32; ++kk) mx = fmaxf(mx, pg[lane * 33 + kk]);
    float sum = 0.f;
    for (int kk = 0; kk < 32; ++kk) {
        float e = __expf(pg[lane * 33 + kk] - mx);
        pg[lane * 33 + kk] = e;
        sum += e;
    }
    const float inv = 1.f / sum;
    __syncwarp();

    const size_t ob = ((size_t)(b * NTOK + lane * BLKT)) * DMODEL + h * DK;
    for (int d = 0; d < 64; ++d) {
        float acc = 0.f;
        for (int kk = 0; kk < 32; ++kk)
            acc += pg[lane * 33 + kk] * vg[kk * 65 + d];
        g_o[ob + d] += acc * inv;
    }
}

// ---------------------------------------------------------------------------
extern "C" void kernel_launch(void* const* d_in, const int* in_sizes, int n_in,
                              void* d_out, int out_size)
{
    const float* x  = (const float*)d_in[0];
    const float* Wq = (const float*)d_in[1];
    const float* Wk = (const float*)d_in[2];
    const float* Wv = (const float*)d_in[3];
    const float* Wo = (const float*)d_in[4];
    const float* bo = (const float*)d_in[5];
    float* out = (float*)d_out;

    float *qkv = nullptr, *osc = nullptr;
    __nv_bfloat16 *xh, *xl, *wh, *wl, *oh, *ol;
    cudaGetSymbolAddress((void**)&qkv, g_qkv);
    cudaGetSymbolAddress((void**)&osc, g_o);
    cudaGetSymbolAddress((void**)&xh, g_xh);
    cudaGetSymbolAddress((void**)&xl, g_xl);
    cudaGetSymbolAddress((void**)&wh, g_wh);
    cudaGetSymbolAddress((void**)&wl, g_wl);
    cudaGetSymbolAddress((void**)&oh, g_oh);
    cudaGetSymbolAddress((void**)&ol, g_ol);

    const int WN = DMODEL * DMODEL;   // 1M elems per weight

    // 0) split inputs into bf16 hi/lo planes
    split_hilo<<<(MROWS * DMODEL / 4 + 255) / 256, 256>>>(x, xh, xl, MROWS * DMODEL);
    split_hilo<<<(WN / 4 + 255) / 256, 256>>>(Wq, wh,            wl,            WN);
    split_hilo<<<(WN / 4 + 255) / 256, 256>>>(Wk, wh + (size_t)WN,     wl + (size_t)WN,     WN);
    split_hilo<<<(WN / 4 + 255) / 256, 256>>>(Wv, wh + (size_t)2 * WN, wl + (size_t)2 * WN, WN);
    split_hilo<<<(WN / 4 + 255) / 256, 256>>>(Wo, wh + (size_t)3 * WN, wl + (size_t)3 * WN, WN);

    // 1) QKV projection -> g_qkv [16512 x 3072]
    const int gsmem = 2 * STAGE_E * (int)sizeof(__nv_bfloat16);   // 81920B
    cudaFuncSetAttribute(gemm_bf16x3,
                         cudaFuncAttributeMaxDynamicSharedMemorySize, gsmem);
    gemm_bf16x3<<<dim3(MROWS / 128, QKVC / 128), 256, gsmem>>>(
        xh, xl, wh, wl, nullptr, qkv, DMODEL, QKVC);

    // 2) block-local attention -> g_o
    const size_t smem = (2 * BLKT * 68 + 8 * 128 + 8 * 264) * sizeof(float);
    cudaFuncSetAttribute(attn_local,
                         cudaFuncAttributeMaxDynamicSharedMemorySize, (int)smem);
    attn_local<<<dim3(HEADS, NBLK, BATCH), 256, smem>>>();

    // 3) global leader attention (adds into g_o)
    attn_global<<<BATCH * HEADS, 32>>>();

    // 4) split attention output, then out = g_o @ Wo^T + bo
    split_hilo<<<(MROWS * DMODEL / 4 + 255) / 256, 256>>>(osc, oh, ol, MROWS * DMODEL);
    gemm_bf16x3<<<dim3(MROWS / 128, DMODEL / 128), 256, gsmem>>>(
        oh, ol, wh + (size_t)3 * WN, wl + (size_t)3 * WN, bo, out, DMODEL, DMODEL);
}

// round 5
// speedup vs baseline: 1.8122x; 1.0322x over previous
#include <cuda_runtime.h>
#include <cuda_bf16.h>
#include <math_constants.h>
#include <cstdint>
#include <cstddef>

#define HEADS  16
#define DK     64
#define BLKT   129
#define NBLK   32
#define BATCH  4
#define NTOK   (BLKT * NBLK)        // 4128
#define MROWS  (BATCH * NTOK)       // 16512
#define DMODEL 1024
#define QKVC   3072
#define WROWS  4096

// Scratch (allocation-free rule: __device__ globals)
__device__ float g_qkv[(size_t)MROWS * QKVC];
__device__ float g_o[(size_t)MROWS * DMODEL];
__device__ __nv_bfloat16 g_xh[(size_t)MROWS * DMODEL];
__device__ __nv_bfloat16 g_xl[(size_t)MROWS * DMODEL];
__device__ __nv_bfloat16 g_wh[(size_t)WROWS * DMODEL];
__device__ __nv_bfloat16 g_wl[(size_t)WROWS * DMODEL];
__device__ __nv_bfloat16 g_oh[(size_t)MROWS * DMODEL];
__device__ __nv_bfloat16 g_ol[(size_t)MROWS * DMODEL];

// ---------------------------------------------------------------------------
// fp32 -> (hi, lo) bf16 split
// ---------------------------------------------------------------------------
__global__ void split_hilo(const float* __restrict__ in,
                           __nv_bfloat16* __restrict__ hi,
                           __nv_bfloat16* __restrict__ lo, int n)
{
    int i = (blockIdx.x * blockDim.x + threadIdx.x) * 4;
    if (i >= n) return;
    float4 v = *(const float4*)(in + i);
    __nv_bfloat16 h0 = __float2bfloat16(v.x);
    __nv_bfloat16 h1 = __float2bfloat16(v.y);
    __nv_bfloat16 h2 = __float2bfloat16(v.z);
    __nv_bfloat16 h3 = __float2bfloat16(v.w);
    __nv_bfloat16 l0 = __float2bfloat16(v.x - __bfloat162float(h0));
    __nv_bfloat16 l1 = __float2bfloat16(v.y - __bfloat162float(h1));
    __nv_bfloat16 l2 = __float2bfloat16(v.z - __bfloat162float(h2));
    __nv_bfloat16 l3 = __float2bfloat16(v.w - __bfloat162float(h3));
    *(__nv_bfloat162*)(hi + i)     = __nv_bfloat162(h0, h1);
    *(__nv_bfloat162*)(hi + i + 2) = __nv_bfloat162(h2, h3);
    *(__nv_bfloat162*)(lo + i)     = __nv_bfloat162(l0, l1);
    *(__nv_bfloat162*)(lo + i + 2) = __nv_bfloat162(l2, l3);
}

// ---------------------------------------------------------------------------
// bf16x3 tensor-core GEMM (NT): C[m,n] = sum_k A[m,k]*B[n,k] (+bias)
// C = Ah*Bh + Ah*Bl + Al*Bh.  CTA 128x128, BK=32, 8 warps of 64x32,
// mma.m16n8k16 with ldmatrix.x4 fragments, 3-stage cp.async pipeline.
// Stage layout: 4 planes (Ah|Al|Bh|Bl) of 128 rows x 40 elems (80B stride,
// ldmatrix conflict-free).
// ---------------------------------------------------------------------------
#define NSTG    3
#define PLANE_B 10240                // 128*40*2 bytes
#define STAGE_B (4 * PLANE_B)        // 40960
#define AOF_H   0
#define AOF_L   PLANE_B
#define BOF_H   (2 * PLANE_B)
#define BOF_L   (3 * PLANE_B)
#define GSMEM   (NSTG * STAGE_B)     // 122880

__device__ __forceinline__ void cpa16(uint32_t dst, const void* src) {
    asm volatile("cp.async.cg.shared.global [%0], [%1], 16;\n" :: "r"(dst), "l"(src));
}
__device__ __forceinline__ void ldsm4(uint32_t* r, uint32_t addr) {
    asm volatile("ldmatrix.sync.aligned.m8n8.x4.shared.b16 {%0,%1,%2,%3}, [%4];"
                 : "=r"(r[0]), "=r"(r[1]), "=r"(r[2]), "=r"(r[3]) : "r"(addr));
}
__device__ __forceinline__ void mma16816(float* c, const uint32_t* a, const uint32_t* b) {
    asm volatile(
        "mma.sync.aligned.m16n8k16.row.col.f32.bf16.bf16.f32 "
        "{%0,%1,%2,%3}, {%4,%5,%6,%7}, {%8,%9}, {%0,%1,%2,%3};\n"
        : "+f"(c[0]), "+f"(c[1]), "+f"(c[2]), "+f"(c[3])
        : "r"(a[0]), "r"(a[1]), "r"(a[2]), "r"(a[3]), "r"(b[0]), "r"(b[1]));
}

__global__ __launch_bounds__(256)
void gemm_bf16x3(const __nv_bfloat16* __restrict__ Ahg,
                 const __nv_bfloat16* __restrict__ Alg,
                 const __nv_bfloat16* __restrict__ Bhg,
                 const __nv_bfloat16* __restrict__ Blg,
                 const float* __restrict__ bias,
                 float* __restrict__ C, int K, int ldc)
{
    extern __shared__ __align__(128) char sm[];
    const uint32_t sbase = (uint32_t)__cvta_generic_to_shared(sm);
    const int tid = threadIdx.x;
    const int warp = tid >> 5, lane = tid & 31;
    const int warp_m = warp & 1, warp_n = warp >> 1;   // 2 x 4 warp grid
    const int g = lane >> 2, t = lane & 3;
    const int m0 = blockIdx.x << 7;
    const int n0 = blockIdx.y << 7;
    const int NCH = K >> 5;

    float acc[4][4][4];
#pragma unroll
    for (int i = 0; i < 4; ++i)
#pragma unroll
        for (int j = 0; j < 4; ++j)
#pragma unroll
            for (int r = 0; r < 4; ++r) acc[i][j][r] = 0.f;

    // ldmatrix per-lane source offsets (bytes, within a plane)
    const int a_row = lane & 15;            // row within m16 tile
    const int a_kk  = (lane >> 4) << 3;     // 0 or 8
    const int b_nt  = lane >> 4;            // which n8 tile of the pair
    const int b_row = lane & 7;
    const int b_kk  = ((lane >> 3) & 1) << 3;
    const uint32_t a_base = (uint32_t)(((warp_m * 64 + a_row) * 40 + a_kk) * 2);
    const uint32_t b_base = (uint32_t)(((warp_n * 32 + b_nt * 8 + b_row) * 40 + b_kk) * 2);

    auto load_chunk = [&](int chunk) {
        const uint32_t s = sbase + (uint32_t)(chunk % NSTG) * STAGE_B;
        const int k0 = chunk << 5;
#pragma unroll
        for (int i = 0; i < 2; ++i) {              // 512 chunks per plane
            int idx = tid + (i << 8);
            int r = idx >> 2, c = idx & 3;         // row 0..127, 16B chunk 0..3
            uint32_t so = (uint32_t)(r * 80 + c * 16);
            size_t ga = (size_t)(m0 + r) * K + k0 + c * 8;
            size_t gb = (size_t)(n0 + r) * K + k0 + c * 8;
            cpa16(s + AOF_H + so, Ahg + ga);
            cpa16(s + AOF_L + so, Alg + ga);
            cpa16(s + BOF_H + so, Bhg + gb);
            cpa16(s + BOF_L + so, Blg + gb);
        }
    };

    auto compute = [&](int st) {
        const uint32_t s = sbase + (uint32_t)st * STAGE_B;
        const uint32_t ah_p = s + AOF_H + a_base;
        const uint32_t al_p = s + AOF_L + a_base;
        const uint32_t bh_p = s + BOF_H + b_base;
        const uint32_t bl_p = s + BOF_L + b_base;
#pragma unroll
        for (int ks = 0; ks < 2; ++ks) {
            const uint32_t ko = (uint32_t)(ks * 32);   // 16 elems * 2B
            uint32_t ah[4][4], al[4][4], bh[2][4], bl[2][4];
#pragma unroll
            for (int i = 0; i < 4; ++i) {
                ldsm4(ah[i], ah_p + (uint32_t)(i * 1280) + ko);
                ldsm4(al[i], al_p + (uint32_t)(i * 1280) + ko);
            }
#pragma unroll
            for (int jp = 0; jp < 2; ++jp) {
                ldsm4(bh[jp], bh_p + (uint32_t)(jp * 1280) + ko);
                ldsm4(bl[jp], bl_p + (uint32_t)(jp * 1280) + ko);
            }
#pragma unroll
            for (int i = 0; i < 4; ++i)
#pragma unroll
                for (int j = 0; j < 4; ++j) {
                    const uint32_t* bhj = &bh[j >> 1][(j & 1) * 2];
                    const uint32_t* blj = &bl[j >> 1][(j & 1) * 2];
                    mma16816(acc[i][j], ah[i], bhj);
                    mma16816(acc[i][j], ah[i], blj);
                    mma16816(acc[i][j], al[i], bhj);
                }
        }
    };

    load_chunk(0);
    asm volatile("cp.async.commit_group;\n");
    load_chunk(1);
    asm volatile("cp.async.commit_group;\n");

    for (int it = 0; it < NCH; ++it) {
        asm volatile("cp.async.wait_group %0;\n" :: "n"(NSTG - 2));
        __syncthreads();
        compute(it % NSTG);
        __syncthreads();
        if (it + NSTG - 1 < NCH) load_chunk(it + NSTG - 1);
        asm volatile("cp.async.commit_group;\n");
    }

    float bv8[8];
#pragma unroll
    for (int j = 0; j < 4; ++j) {
        int col = n0 + warp_n * 32 + j * 8 + 2 * t;
        bv8[j * 2]     = bias ? bias[col] : 0.f;
        bv8[j * 2 + 1] = bias ? bias[col + 1] : 0.f;
    }

#pragma unroll
    for (int i = 0; i < 4; ++i) {
        int row0 = m0 + warp_m * 64 + i * 16 + g;
#pragma unroll
        for (int j = 0; j < 4; ++j) {
            int col = n0 + warp_n * 32 + j * 8 + 2 * t;
            float2 v0 = {acc[i][j][0] + bv8[j * 2], acc[i][j][1] + bv8[j * 2 + 1]};
            float2 v1 = {acc[i][j][2] + bv8[j * 2], acc[i][j][3] + bv8[j * 2 + 1]};
            *(float2*)&C[(size_t)row0 * ldc + col] = v0;
            *(float2*)&C[(size_t)(row0 + 8) * ldc + col] = v1;
        }
    }
}

// ---------------------------------------------------------------------------
// Block-local attention (unchanged, known-good)
// ---------------------------------------------------------------------------
__global__ __launch_bounds__(256, 2)
void attn_local()
{
    const int h = blockIdx.x, nb = blockIdx.y, b = blockIdx.z;
    const int tid = threadIdx.x, warp = tid >> 5, lane = tid & 31;
    extern __shared__ float smf[];
    float* Ks = smf;
    float* Vs = Ks + BLKT * 68;
    float* Qs = Vs + BLKT * 68;
    float* Ps = Qs + 8 * 128;

    const size_t base = ((size_t)(b * NTOK + nb * BLKT)) * QKVC + h * DK;

    for (int f = tid; f < BLKT * 16; f += 256) {
        int r = f >> 4, c4 = (f & 15) << 2;
        *(float4*)&Ks[r * 68 + c4] =
            *(const float4*)&g_qkv[base + 1024 + (size_t)r * QKVC + c4];
        *(float4*)&Vs[r * 68 + c4] =
            *(const float4*)&g_qkv[base + 2048 + (size_t)r * QKVC + c4];
    }
    __syncthreads();

    const float scale = 0.125f;
    const int half = lane >> 4;
    const int dl = (lane & 15) << 2;
    float* Qw = Qs + warp * 128;
    float* Pw = Ps + warp * 264;

    for (int p = warp; p < 65; p += 8) {
        const int r0 = p * 2;
        const bool has1 = (r0 + 1) < BLKT;
        const int r1m = has1 ? r0 + 1 : r0;
        Qw[lane]      = g_qkv[base + (size_t)r0 * QKVC + lane];
        Qw[lane + 32] = g_qkv[base + (size_t)r0 * QKVC + lane + 32];
        Qw[64 + lane]      = g_qkv[base + (size_t)r1m * QKVC + lane];
        Qw[64 + lane + 32] = g_qkv[base + (size_t)r1m * QKVC + lane + 32];
        __syncwarp();

        float s0[5], s1[5];
#pragma unroll
        for (int jj = 0; jj < 5; ++jj) {
            const int j = lane + (jj << 5);
            float a0 = 0.f, a1 = 0.f;
            if (j < BLKT) {
                const float* kr = Ks + j * 68;
#pragma unroll
                for (int d4 = 0; d4 < 16; ++d4) {
                    float4 kk4 = *(const float4*)&kr[d4 << 2];
                    float4 q0  = *(const float4*)&Qw[d4 << 2];
                    float4 q1  = *(const float4*)&Qw[64 + (d4 << 2)];
                    a0 += kk4.x * q0.x + kk4.y * q0.y + kk4.z * q0.z + kk4.w * q0.w;
                    a1 += kk4.x * q1.x + kk4.y * q1.y + kk4.z * q1.z + kk4.w * q1.w;
                }
            }
            s0[jj] = (j < BLKT) ? a0 * scale : -CUDART_INF_F;
            s1[jj] = (j < BLKT) ? a1 * scale : -CUDART_INF_F;
        }

        float m0 = s0[0], m1 = s1[0];
#pragma unroll
        for (int jj = 1; jj < 5; ++jj) { m0 = fmaxf(m0, s0[jj]); m1 = fmaxf(m1, s1[jj]); }
#pragma unroll
        for (int o = 16; o > 0; o >>= 1) {
            m0 = fmaxf(m0, __shfl_xor_sync(0xffffffffu, m0, o));
            m1 = fmaxf(m1, __shfl_xor_sync(0xffffffffu, m1, o));
        }
        float e0[5], e1[5], sum0 = 0.f, sum1 = 0.f;
#pragma unroll
        for (int jj = 0; jj < 5; ++jj) {
            const int j = lane + (jj << 5);
            e0[jj] = (j < BLKT) ? __expf(s0[jj] - m0) : 0.f;
            e1[jj] = (j < BLKT) ? __expf(s1[jj] - m1) : 0.f;
            sum0 += e0[jj]; sum1 += e1[jj];
        }
#pragma unroll
        for (int o = 16; o > 0; o >>= 1) {
            sum0 += __shfl_xor_sync(0xffffffffu, sum0, o);
            sum1 += __shfl_xor_sync(0xffffffffu, sum1, o);
        }
        const float i0 = 1.f / sum0, i1 = 1.f / sum1;
#pragma unroll
        for (int jj = 0; jj < 5; ++jj) {
            const int j = lane + (jj << 5);
            if (j < BLKT) { Pw[j] = e0[jj] * i0; Pw[132 + j] = e1[jj] * i1; }
        }
        __syncwarp();

        float4 o0 = {0, 0, 0, 0}, o1 = {0, 0, 0, 0};
        const int kbase = half * 65;
        for (int tt = 0; tt < 65; ++tt) {
            const int key = kbase + tt;
            if (key < BLKT) {
                const float p0 = Pw[key], p1 = Pw[132 + key];
                float4 vv = *(const float4*)&Vs[key * 68 + dl];
                o0.x += p0 * vv.x; o0.y += p0 * vv.y; o0.z += p0 * vv.z; o0.w += p0 * vv.w;
                o1.x += p1 * vv.x; o1.y += p1 * vv.y; o1.z += p1 * vv.z; o1.w += p1 * vv.w;
            }
        }
        o0.x += __shfl_xor_sync(0xffffffffu, o0.x, 16);
        o0.y += __shfl_xor_sync(0xffffffffu, o0.y, 16);
        o0.z += __shfl_xor_sync(0xffffffffu, o0.z, 16);
        o0.w += __shfl_xor_sync(0xffffffffu, o0.w, 16);
        o1.x += __shfl_xor_sync(0xffffffffu, o1.x, 16);
        o1.y += __shfl_xor_sync(0xffffffffu, o1.y, 16);
        o1.z += __shfl_xor_sync(0xffffffffu, o1.z, 16);
        o1.w += __shfl_xor_sync(0xffffffffu, o1.w, 16);

        const size_t obase = ((size_t)(b * NTOK + nb * BLKT)) * DMODEL + h * DK;
        if (lane < 16) {
            *(float4*)&g_o[obase + (size_t)r0 * DMODEL + dl] = o0;
            if (has1)
                *(float4*)&g_o[obase + (size_t)(r0 + 1) * DMODEL + dl] = o1;
        }
        __syncwarp();
    }
}

// ---------------------------------------------------------------------------
// Global (block-leader) attention (unchanged)
// ---------------------------------------------------------------------------
__global__ void attn_global()
{
    const int b = blockIdx.x >> 4, h = blockIdx.x & 15;
    const int lane = threadIdx.x;
    __shared__ float kg[32 * 65], vg[32 * 65], qg[32 * 65], pg[32 * 33];

    const size_t rb = ((size_t)(b * NTOK + lane * BLKT)) * QKVC + h * DK;
    for (int d = 0; d < 64; ++d) {
        qg[lane * 65 + d] = g_qkv[rb + d];
        kg[lane * 65 + d] = g_qkv[rb + 1024 + d];
        vg[lane * 65 + d] = g_qkv[rb + 2048 + d];
    }
    __syncwarp();

    for (int kk = 0; kk < 32; ++kk) {
        float a = 0.f;
        for (int d = 0; d < 64; ++d) a += qg[lane * 65 + d] * kg[kk * 65 + d];
        pg[lane * 33 + kk] = a * 0.125f;
    }
    float mx = -CUDART_INF_F;
    for (int kk = 0; kk < 32; ++kk) mx = fmaxf(mx, pg[lane * 33 + kk]);
    float sum = 0.f;
    for (int kk = 0; kk < 32; ++kk) {
        float e = __expf(pg[lane * 33 + kk] - mx);
        pg[lane * 33 + kk] = e;
        sum += e;
    }
    const float inv = 1.f / sum;
    __syncwarp();

    const size_t ob = ((size_t)(b * NTOK + lane * BLKT)) * DMODEL + h * DK;
    for (int d = 0; d < 64; ++d) {
        float acc = 0.f;
        for (int kk = 0; kk < 32; ++kk)
            acc += pg[lane * 33 + kk] * vg[kk * 65 + d];
        g_o[ob + d] += acc * inv;
    }
}

// ---------------------------------------------------------------------------
extern "C" void kernel_launch(void* const* d_in, const int* in_sizes, int n_in,
                              void* d_out, int out_size)
{
    const float* x  = (const float*)d_in[0];
    const float* Wq = (const float*)d_in[1];
    const float* Wk = (const float*)d_in[2];
    const float* Wv = (const float*)d_in[3];
    const float* Wo = (const float*)d_in[4];
    const float* bo = (const float*)d_in[5];
    float* out = (float*)d_out;

    float *qkv = nullptr, *osc = nullptr;
    __nv_bfloat16 *xh, *xl, *wh, *wl, *oh, *ol;
    cudaGetSymbolAddress((void**)&qkv, g_qkv);
    cudaGetSymbolAddress((void**)&osc, g_o);
    cudaGetSymbolAddress((void**)&xh, g_xh);
    cudaGetSymbolAddress((void**)&xl, g_xl);
    cudaGetSymbolAddress((void**)&wh, g_wh);
    cudaGetSymbolAddress((void**)&wl, g_wl);
    cudaGetSymbolAddress((void**)&oh, g_oh);
    cudaGetSymbolAddress((void**)&ol, g_ol);

    const int WN = DMODEL * DMODEL;

    // 0) split inputs into bf16 hi/lo planes
    split_hilo<<<(MROWS * DMODEL / 4 + 255) / 256, 256>>>(x, xh, xl, MROWS * DMODEL);
    split_hilo<<<(WN / 4 + 255) / 256, 256>>>(Wq, wh,                  wl,                  WN);
    split_hilo<<<(WN / 4 + 255) / 256, 256>>>(Wk, wh + (size_t)WN,     wl + (size_t)WN,     WN);
    split_hilo<<<(WN / 4 + 255) / 256, 256>>>(Wv, wh + (size_t)2 * WN, wl + (size_t)2 * WN, WN);
    split_hilo<<<(WN / 4 + 255) / 256, 256>>>(Wo, wh + (size_t)3 * WN, wl + (size_t)3 * WN, WN);

    // 1) QKV projection -> g_qkv
    cudaFuncSetAttribute(gemm_bf16x3,
                         cudaFuncAttributeMaxDynamicSharedMemorySize, GSMEM);
    gemm_bf16x3<<<dim3(MROWS / 128, QKVC / 128), 256, GSMEM>>>(
        xh, xl, wh, wl, nullptr, qkv, DMODEL, QKVC);

    // 2) block-local attention -> g_o
    const size_t smem = (2 * BLKT * 68 + 8 * 128 + 8 * 264) * sizeof(float);
    cudaFuncSetAttribute(attn_local,
                         cudaFuncAttributeMaxDynamicSharedMemorySize, (int)smem);
    attn_local<<<dim3(HEADS, NBLK, BATCH), 256, smem>>>();

    // 3) global leader attention (adds into g_o)
    attn_global<<<BATCH * HEADS, 32>>>();

    // 4) split attention output, then out = g_o @ Wo^T + bo
    split_hilo<<<(MROWS * DMODEL / 4 + 255) / 256, 256>>>(osc, oh, ol, MROWS * DMODEL);
    gemm_bf16x3<<<dim3(MROWS / 128, DMODEL / 128), 256, GSMEM>>>(
        oh, ol, wh + (size_t)3 * WN, wl + (size_t)3 * WN, bo, out, DMODEL, DMODEL);
}

// round 8
// speedup vs baseline: 1.9470x; 1.0744x over previous
#include <cuda_runtime.h>
#include <cuda_bf16.h>
#include <cuda_fp16.h>
#include <math_constants.h>
#include <cstdint>
#include <cstddef>

#define HEADS  16
#define DK     64
#define BLKT   129
#define NBLK   32
#define BATCH  4
#define NTOK   (BLKT * NBLK)        // 4128
#define MROWS  (BATCH * NTOK)       // 16512
#define DMODEL 1024
#define QKVC   3072
#define WN     (DMODEL * DMODEL)    // 1M

// Scratch (allocation-free rule: __device__ globals)
__device__ float g_qkv[(size_t)MROWS * QKVC];
__device__ float g_o[(size_t)MROWS * DMODEL];
__device__ __nv_bfloat16 g_xh[(size_t)MROWS * DMODEL];
__device__ __nv_bfloat16 g_xl[(size_t)MROWS * DMODEL];
__device__ __nv_bfloat16 g_wh[(size_t)3 * WN];
__device__ __nv_bfloat16 g_wl[(size_t)3 * WN];
__device__ __half g_woh[(size_t)WN];
__device__ __half g_wol[(size_t)WN];
__device__ __half g_oh[(size_t)MROWS * DMODEL];

// ---------------------------------------------------------------------------
// Split / round kernels
// ---------------------------------------------------------------------------
__global__ void split_bf16(const float* __restrict__ in,
                           __nv_bfloat16* __restrict__ hi,
                           __nv_bfloat16* __restrict__ lo, int n)
{
    int i = (blockIdx.x * blockDim.x + threadIdx.x) * 4;
    if (i >= n) return;
    float4 v = *(const float4*)(in + i);
    __nv_bfloat16 h0 = __float2bfloat16(v.x), h1 = __float2bfloat16(v.y);
    __nv_bfloat16 h2 = __float2bfloat16(v.z), h3 = __float2bfloat16(v.w);
    *(__nv_bfloat162*)(hi + i)     = __nv_bfloat162(h0, h1);
    *(__nv_bfloat162*)(hi + i + 2) = __nv_bfloat162(h2, h3);
    *(__nv_bfloat162*)(lo + i) = __nv_bfloat162(
        __float2bfloat16(v.x - __bfloat162float(h0)),
        __float2bfloat16(v.y - __bfloat162float(h1)));
    *(__nv_bfloat162*)(lo + i + 2) = __nv_bfloat162(
        __float2bfloat16(v.z - __bfloat162float(h2)),
        __float2bfloat16(v.w - __bfloat162float(h3)));
}

// fused Wq/Wk/Wv split (blockIdx.y selects weight)
__global__ void split_w3(const float* __restrict__ Wq, const float* __restrict__ Wk,
                         const float* __restrict__ Wv,
                         __nv_bfloat16* __restrict__ hi, __nv_bfloat16* __restrict__ lo)
{
    const int w = blockIdx.y;
    const float* src = (w == 0) ? Wq : (w == 1) ? Wk : Wv;
    size_t off = (size_t)w * WN;
    int i = (blockIdx.x * blockDim.x + threadIdx.x) * 4;
    if (i >= WN) return;
    float4 v = *(const float4*)(src + i);
    __nv_bfloat16 h0 = __float2bfloat16(v.x), h1 = __float2bfloat16(v.y);
    __nv_bfloat16 h2 = __float2bfloat16(v.z), h3 = __float2bfloat16(v.w);
    *(__nv_bfloat162*)(hi + off + i)     = __nv_bfloat162(h0, h1);
    *(__nv_bfloat162*)(hi + off + i + 2) = __nv_bfloat162(h2, h3);
    *(__nv_bfloat162*)(lo + off + i) = __nv_bfloat162(
        __float2bfloat16(v.x - __bfloat162float(h0)),
        __float2bfloat16(v.y - __bfloat162float(h1)));
    *(__nv_bfloat162*)(lo + off + i + 2) = __nv_bfloat162(
        __float2bfloat16(v.z - __bfloat162float(h2)),
        __float2bfloat16(v.w - __bfloat162float(h3)));
}

__global__ void split_fp16(const float* __restrict__ in,
                           __half* __restrict__ hi, __half* __restrict__ lo, int n)
{
    int i = (blockIdx.x * blockDim.x + threadIdx.x) * 4;
    if (i >= n) return;
    float4 v = *(const float4*)(in + i);
    __half h0 = __float2half(v.x), h1 = __float2half(v.y);
    __half h2 = __float2half(v.z), h3 = __float2half(v.w);
    *(__half2*)(hi + i)     = __half2(h0, h1);
    *(__half2*)(hi + i + 2) = __half2(h2, h3);
    *(__half2*)(lo + i) = __half2(__float2half(v.x - __half2float(h0)),
                                  __float2half(v.y - __half2float(h1)));
    *(__half2*)(lo + i + 2) = __half2(__float2half(v.z - __half2float(h2)),
                                      __float2half(v.w - __half2float(h3)));
}

__global__ void round_fp16(const float* __restrict__ in, __half* __restrict__ out, int n)
{
    int i = (blockIdx.x * blockDim.x + threadIdx.x) * 4;
    if (i >= n) return;
    float4 v = *(const float4*)(in + i);
    *(__half2*)(out + i)     = __half2(__float2half(v.x), __float2half(v.y));
    *(__half2*)(out + i + 2) = __half2(__float2half(v.z), __float2half(v.w));
}

// ---------------------------------------------------------------------------
// Tensor-core GEMM (NT): C[m,n] = sum_k A[m,k]*B[n,k] (+bias)
// TM=128, TN=256, BK=32, 8 warps (2m x 4n grid, 64x64 warp tiles),
// mma.m16n8k16 + ldmatrix.x4, 3-stage cp.async.
// NPASS=3 (bf16): C = Ah*Bh + Ah*Bl + Al*Bh   (QKV, ~2^-18 accurate)
// NPASS=2 (fp16): C = Ah*(Bh+Bl)              (out-proj)
// ---------------------------------------------------------------------------
#define NSTG 3

__device__ __forceinline__ void cpa16(uint32_t dst, const void* src) {
    asm volatile("cp.async.cg.shared.global [%0], [%1], 16;\n" :: "r"(dst), "l"(src));
}
__device__ __forceinline__ void ldsm4(uint32_t* r, uint32_t addr) {
    asm volatile("ldmatrix.sync.aligned.m8n8.x4.shared.b16 {%0,%1,%2,%3}, [%4];"
                 : "=r"(r[0]), "=r"(r[1]), "=r"(r[2]), "=r"(r[3]) : "r"(addr));
}
__device__ __forceinline__ void mma_bf16(float* c, const uint32_t* a, const uint32_t* b) {
    asm volatile(
        "mma.sync.aligned.m16n8k16.row.col.f32.bf16.bf16.f32 "
        "{%0,%1,%2,%3}, {%4,%5,%6,%7}, {%8,%9}, {%0,%1,%2,%3};\n"
        : "+f"(c[0]), "+f"(c[1]), "+f"(c[2]), "+f"(c[3])
        : "r"(a[0]), "r"(a[1]), "r"(a[2]), "r"(a[3]), "r"(b[0]), "r"(b[1]));
}
__device__ __forceinline__ void mma_fp16(float* c, const uint32_t* a, const uint32_t* b) {
    asm volatile(
        "mma.sync.aligned.m16n8k16.row.col.f32.f16.f16.f32 "
        "{%0,%1,%2,%3}, {%4,%5,%6,%7}, {%8,%9}, {%0,%1,%2,%3};\n"
        : "+f"(c[0]), "+f"(c[1]), "+f"(c[2]), "+f"(c[3])
        : "r"(a[0]), "r"(a[1]), "r"(a[2]), "r"(a[3]), "r"(b[0]), "r"(b[1]));
}

template<typename T, int NPASS>
__global__ __launch_bounds__(256)
void gemm_tc(const T* __restrict__ Ahg, const T* __restrict__ Alg,
             const T* __restrict__ Bhg, const T* __restrict__ Blg,
             const float* __restrict__ bias,
             float* __restrict__ C, int K, int ldc)
{
    constexpr int APL   = (NPASS == 3) ? 2 : 1;        // A planes
    constexpr int APB   = 10240;                        // 128 rows * 80B
    constexpr int BPB   = 20480;                        // 256 rows * 80B
    constexpr int BOFF  = APL * APB;
    constexpr int STGB  = APL * APB + 2 * BPB;

    extern __shared__ __align__(128) char smc[];
    const uint32_t sbase = (uint32_t)__cvta_generic_to_shared(smc);
    const int tid = threadIdx.x;
    const int warp = tid >> 5, lane = tid & 31;
    const int warp_m = warp & 1, warp_n = warp >> 1;    // 2 x 4
    const int g = lane >> 2, t = lane & 3;
    const int m0 = blockIdx.x << 7;
    const int n0 = blockIdx.y << 8;
    const int NCH = K >> 5;

    float acc[4][8][4];
#pragma unroll
    for (int i = 0; i < 4; ++i)
#pragma unroll
        for (int j = 0; j < 8; ++j)
#pragma unroll
            for (int r = 0; r < 4; ++r) acc[i][j][r] = 0.f;

    // ldmatrix lane addressing
    const int a_row = lane & 15;
    const int a_k16 = (lane >> 4) << 4;                 // byte offset 0/16
    const int b_nt  = lane >> 4;
    const int b_row = lane & 7;
    const int b_k16 = ((lane >> 3) & 1) << 4;
    const uint32_t a_base = (uint32_t)((warp_m * 64 + a_row) * 80 + a_k16);
    const uint32_t b_base = (uint32_t)((warp_n * 64 + b_nt * 8 + b_row) * 80 + b_k16);

    auto load_chunk = [&](int chunk) {
        const uint32_t s = sbase + (uint32_t)(chunk % NSTG) * STGB;
        const int k0 = chunk << 5;
        // A planes: 512 x 16B each
#pragma unroll
        for (int i = 0; i < 2; ++i) {
            int idx = tid + (i << 8);
            int r = idx >> 2, c = idx & 3;
            uint32_t so = (uint32_t)(r * 80 + c * 16);
            size_t ga = (size_t)(m0 + r) * K + k0 + c * 8;
            cpa16(s + so, Ahg + ga);
            if (NPASS == 3) cpa16(s + APB + so, Alg + ga);
        }
        // B planes: 1024 x 16B each
#pragma unroll
        for (int i = 0; i < 4; ++i) {
            int idx = tid + (i << 8);
            int r = idx >> 2, c = idx & 3;
            uint32_t so = (uint32_t)(r * 80 + c * 16);
            size_t gb = (size_t)(n0 + r) * K + k0 + c * 8;
            cpa16(s + BOFF + so, Bhg + gb);
            cpa16(s + BOFF + BPB + so, Blg + gb);
        }
    };

    auto compute = [&](int st) {
        const uint32_t s = sbase + (uint32_t)st * STGB;
#pragma unroll
        for (int ks = 0; ks < 2; ++ks) {
            const uint32_t ko = (uint32_t)(ks * 32);
            uint32_t ah[4][4], al[4][4];
#pragma unroll
            for (int i = 0; i < 4; ++i) {
                ldsm4(ah[i], s + a_base + (uint32_t)(i * 1280) + ko);
                if (NPASS == 3)
                    ldsm4(al[i], s + APB + a_base + (uint32_t)(i * 1280) + ko);
            }
#pragma unroll
            for (int jp = 0; jp < 4; ++jp) {
                uint32_t bh[4], bl[4];
                ldsm4(bh, s + BOFF + b_base + (uint32_t)(jp * 1280) + ko);
                ldsm4(bl, s + BOFF + BPB + b_base + (uint32_t)(jp * 1280) + ko);
#pragma unroll
                for (int i = 0; i < 4; ++i)
#pragma unroll
                    for (int jj = 0; jj < 2; ++jj) {
                        float* cc = acc[i][jp * 2 + jj];
                        if (NPASS == 3) {
                            mma_bf16(cc, ah[i], &bh[jj * 2]);
                            mma_bf16(cc, ah[i], &bl[jj * 2]);
                            mma_bf16(cc, al[i], &bh[jj * 2]);
                        } else {
                            mma_fp16(cc, ah[i], &bh[jj * 2]);
                            mma_fp16(cc, ah[i], &bl[jj * 2]);
                        }
                    }
            }
        }
    };

    load_chunk(0);
    asm volatile("cp.async.commit_group;\n");
    load_chunk(1);
    asm volatile("cp.async.commit_group;\n");

    for (int it = 0; it < NCH; ++it) {
        asm volatile("cp.async.wait_group %0;\n" :: "n"(NSTG - 2));
        __syncthreads();
        compute(it % NSTG);
        __syncthreads();
        if (it + NSTG - 1 < NCH) load_chunk(it + NSTG - 1);
        asm volatile("cp.async.commit_group;\n");
    }

#pragma unroll
    for (int i = 0; i < 4; ++i) {
        int row0 = m0 + warp_m * 64 + i * 16 + g;
#pragma unroll
        for (int j = 0; j < 8; ++j) {
            int col = n0 + warp_n * 64 + j * 8 + 2 * t;
            float b0 = bias ? bias[col] : 0.f;
            float b1 = bias ? bias[col + 1] : 0.f;
            float2 v0 = {acc[i][j][0] + b0, acc[i][j][1] + b1};
            float2 v1 = {acc[i][j][2] + b0, acc[i][j][3] + b1};
            *(float2*)&C[(size_t)row0 * ldc + col] = v0;
            *(float2*)&C[(size_t)(row0 + 8) * ldc + col] = v1;
        }
    }
}

// ---------------------------------------------------------------------------
// Block-local attention (unchanged, known-good)
// ---------------------------------------------------------------------------
__global__ __launch_bounds__(256, 2)
void attn_local()
{
    const int h = blockIdx.x, nb = blockIdx.y, b = blockIdx.z;
    const int tid = threadIdx.x, warp = tid >> 5, lane = tid & 31;
    extern __shared__ float smf[];
    float* Ks = smf;
    float* Vs = Ks + BLKT * 68;
    float* Qs = Vs + BLKT * 68;
    float* Ps = Qs + 8 * 128;

    const size_t base = ((size_t)(b * NTOK + nb * BLKT)) * QKVC + h * DK;

    for (int f = tid; f < BLKT * 16; f += 256) {
        int r = f >> 4, c4 = (f & 15) << 2;
        *(float4*)&Ks[r * 68 + c4] =
            *(const float4*)&g_qkv[base + 1024 + (size_t)r * QKVC + c4];
        *(float4*)&Vs[r * 68 + c4] =
            *(const float4*)&g_qkv[base + 2048 + (size_t)r * QKVC + c4];
    }
    __syncthreads();

    const float scale = 0.125f;
    const int half = lane >> 4;
    const int dl = (lane & 15) << 2;
    float* Qw = Qs + warp * 128;
    float* Pw = Ps + warp * 264;

    for (int p = warp; p < 65; p += 8) {
        const int r0 = p * 2;
        const bool has1 = (r0 + 1) < BLKT;
        const int r1m = has1 ? r0 + 1 : r0;
        Qw[lane]      = g_qkv[base + (size_t)r0 * QKVC + lane];
        Qw[lane + 32] = g_qkv[base + (size_t)r0 * QKVC + lane + 32];
        Qw[64 + lane]      = g_qkv[base + (size_t)r1m * QKVC + lane];
        Qw[64 + lane + 32] = g_qkv[base + (size_t)r1m * QKVC + lane + 32];
        __syncwarp();

        float s0[5], s1[5];
#pragma unroll
        for (int jj = 0; jj < 5; ++jj) {
            const int j = lane + (jj << 5);
            float a0 = 0.f, a1 = 0.f;
            if (j < BLKT) {
                const float* kr = Ks + j * 68;
#pragma unroll
                for (int d4 = 0; d4 < 16; ++d4) {
                    float4 kk4 = *(const float4*)&kr[d4 << 2];
                    float4 q0  = *(const float4*)&Qw[d4 << 2];
                    float4 q1  = *(const float4*)&Qw[64 + (d4 << 2)];
                    a0 += kk4.x * q0.x + kk4.y * q0.y + kk4.z * q0.z + kk4.w * q0.w;
                    a1 += kk4.x * q1.x + kk4.y * q1.y + kk4.z * q1.z + kk4.w * q1.w;
                }
            }
            s0[jj] = (j < BLKT) ? a0 * scale : -CUDART_INF_F;
            s1[jj] = (j < BLKT) ? a1 * scale : -CUDART_INF_F;
        }

        float m0 = s0[0], m1 = s1[0];
#pragma unroll
        for (int jj = 1; jj < 5; ++jj) { m0 = fmaxf(m0, s0[jj]); m1 = fmaxf(m1, s1[jj]); }
#pragma unroll
        for (int o = 16; o > 0; o >>= 1) {
            m0 = fmaxf(m0, __shfl_xor_sync(0xffffffffu, m0, o));
            m1 = fmaxf(m1, __shfl_xor_sync(0xffffffffu, m1, o));
        }
        float e0[5], e1[5], sum0 = 0.f, sum1 = 0.f;
#pragma unroll
        for (int jj = 0; jj < 5; ++jj) {
            const int j = lane + (jj << 5);
            e0[jj] = (j < BLKT) ? __expf(s0[jj] - m0) : 0.f;
            e1[jj] = (j < BLKT) ? __expf(s1[jj] - m1) : 0.f;
            sum0 += e0[jj]; sum1 += e1[jj];
        }
#pragma unroll
        for (int o = 16; o > 0; o >>= 1) {
            sum0 += __shfl_xor_sync(0xffffffffu, sum0, o);
            sum1 += __shfl_xor_sync(0xffffffffu, sum1, o);
        }
        const float i0 = 1.f / sum0, i1 = 1.f / sum1;
#pragma unroll
        for (int jj = 0; jj < 5; ++jj) {
            const int j = lane + (jj << 5);
            if (j < BLKT) { Pw[j] = e0[jj] * i0; Pw[132 + j] = e1[jj] * i1; }
        }
        __syncwarp();

        float4 o0 = {0, 0, 0, 0}, o1 = {0, 0, 0, 0};
        const int kbase = half * 65;
        for (int tt = 0; tt < 65; ++tt) {
            const int key = kbase + tt;
            if (key < BLKT) {
                const float p0 = Pw[key], p1 = Pw[132 + key];
                float4 vv = *(const float4*)&Vs[key * 68 + dl];
                o0.x += p0 * vv.x; o0.y += p0 * vv.y; o0.z += p0 * vv.z; o0.w += p0 * vv.w;
                o1.x += p1 * vv.x; o1.y += p1 * vv.y; o1.z += p1 * vv.z; o1.w += p1 * vv.w;
            }
        }
        o0.x += __shfl_xor_sync(0xffffffffu, o0.x, 16);
        o0.y += __shfl_xor_sync(0xffffffffu, o0.y, 16);
        o0.z += __shfl_xor_sync(0xffffffffu, o0.z, 16);
        o0.w += __shfl_xor_sync(0xffffffffu, o0.w, 16);
        o1.x += __shfl_xor_sync(0xffffffffu, o1.x, 16);
        o1.y += __shfl_xor_sync(0xffffffffu, o1.y, 16);
        o1.z += __shfl_xor_sync(0xffffffffu, o1.z, 16);
        o1.w += __shfl_xor_sync(0xffffffffu, o1.w, 16);

        const size_t obase = ((size_t)(b * NTOK + nb * BLKT)) * DMODEL + h * DK;
        if (lane < 16) {
            *(float4*)&g_o[obase + (size_t)r0 * DMODEL + dl] = o0;
            if (has1)
                *(float4*)&g_o[obase + (size_t)(r0 + 1) * DMODEL + dl] = o1;
        }
        __syncwarp();
    }
}

// ---------------------------------------------------------------------------
// Global (block-leader) attention (unchanged)
// ---------------------------------------------------------------------------
__global__ void attn_global()
{
    const int b = blockIdx.x >> 4, h = blockIdx.x & 15;
    const int lane = threadIdx.x;
    __shared__ float kg[32 * 65], vg[32 * 65], qg[32 * 65], pg[32 * 33];

    const size_t rb = ((size_t)(b * NTOK + lane * BLKT)) * QKVC + h * DK;
    for (int d = 0; d < 64; ++d) {
        qg[lane * 65 + d] = g_qkv[rb + d];
        kg[lane * 65 + d] = g_qkv[rb + 1024 + d];
        vg[lane * 65 + d] = g_qkv[rb + 2048 + d];
    }
    __syncwarp();

    for (int kk = 0; kk < 32; ++kk) {
        float a = 0.f;
        for (int d = 0; d < 64; ++d) a += qg[lane * 65 + d] * kg[kk * 65 + d];
        pg[lane * 33 + kk] = a * 0.125f;
    }
    float mx = -CUDART_INF_F;
    for (int kk = 0; kk < 32; ++kk) mx = fmaxf(mx, pg[lane * 33 + kk]);
    float sum = 0.f;
    for (int kk = 0; kk < 32; ++kk) {
        float e = __expf(pg[lane * 33 + kk] - mx);
        pg[lane * 33 + kk] = e;
        sum += e;
    }
    const float inv = 1.f / sum;
    __syncwarp();

    const size_t ob = ((size_t)(b * NTOK + lane * BLKT)) * DMODEL + h * DK;
    for (int d = 0; d < 64; ++d) {
        float acc = 0.f;
        for (int kk = 0; kk < 32; ++kk)
            acc += pg[lane * 33 + kk] * vg[kk * 65 + d];
        g_o[ob + d] += acc * inv;
    }
}

// ---------------------------------------------------------------------------
extern "C" void kernel_launch(void* const* d_in, const int* in_sizes, int n_in,
                              void* d_out, int out_size)
{
    const float* x  = (const float*)d_in[0];
    const float* Wq = (const float*)d_in[1];
    const float* Wk = (const float*)d_in[2];
    const float* Wv = (const float*)d_in[3];
    const float* Wo = (const float*)d_in[4];
    const float* bo = (const float*)d_in[5];
    float* out = (float*)d_out;

    float *qkv = nullptr, *osc = nullptr;
    __nv_bfloat16 *xh, *xl, *wh, *wl;
    __half *woh, *wol, *oh;
    cudaGetSymbolAddress((void**)&qkv, g_qkv);
    cudaGetSymbolAddress((void**)&osc, g_o);
    cudaGetSymbolAddress((void**)&xh, g_xh);
    cudaGetSymbolAddress((void**)&xl, g_xl);
    cudaGetSymbolAddress((void**)&wh, g_wh);
    cudaGetSymbolAddress((void**)&wl, g_wl);
    cudaGetSymbolAddress((void**)&woh, g_woh);
    cudaGetSymbolAddress((void**)&wol, g_wol);
    cudaGetSymbolAddress((void**)&oh, g_oh);

    // 0) precision splits
    split_bf16<<<(MROWS * DMODEL / 4 + 255) / 256, 256>>>(x, xh, xl, MROWS * DMODEL);
    split_w3<<<dim3(WN / 4 / 256, 3), 256>>>(Wq, Wk, Wv, wh, wl);
    split_fp16<<<(WN / 4 + 255) / 256, 256>>>(Wo, woh, wol, WN);

    // 1) QKV projection (bf16x3, TN=256)
    constexpr int GS3 = NSTG * (2 * 10240 + 2 * 20480);   // 184320
    constexpr int GS2 = NSTG * (1 * 10240 + 2 * 20480);   // 153600
    auto* f3 = gemm_tc<__nv_bfloat16, 3>;
    auto* f2 = gemm_tc<__half, 2>;
    cudaFuncSetAttribute(f3, cudaFuncAttributeMaxDynamicSharedMemorySize, GS3);
    cudaFuncSetAttribute(f2, cudaFuncAttributeMaxDynamicSharedMemorySize, GS2);
    gemm_tc<__nv_bfloat16, 3><<<dim3(MROWS / 128, QKVC / 256), 256, GS3>>>(
        xh, xl, wh, wl, nullptr, qkv, DMODEL, QKVC);

    // 2) block-local attention -> g_o
    const size_t smem = (2 * BLKT * 68 + 8 * 128 + 8 * 264) * sizeof(float);
    cudaFuncSetAttribute(attn_local,
                         cudaFuncAttributeMaxDynamicSharedMemorySize, (int)smem);
    attn_local<<<dim3(HEADS, NBLK, BATCH), 256, smem>>>();

    // 3) global leader attention (adds into g_o)
    attn_global<<<BATCH * HEADS, 32>>>();

    // 4) out = fp16(g_o) @ (Woh+Wol)^T + bo   (fp16 2-pass, TN=256)
    round_fp16<<<(MROWS * DMODEL / 4 + 255) / 256, 256>>>(osc, oh, MROWS * DMODEL);
    gemm_tc<__half, 2><<<dim3(MROWS / 128, DMODEL / 256), 256, GS2>>>(
        oh, nullptr, woh, wol, bo, out, DMODEL, DMODEL);
}

// round 9
// speedup vs baseline: 2.2818x; 1.1720x over previous
#include <cuda_runtime.h>
#include <cuda_bf16.h>
#include <cuda_fp16.h>
#include <math_constants.h>
#include <cstdint>
#include <cstddef>

#define HEADS  16
#define DK     64
#define BLKT   129
#define NBLK   32
#define BATCH  4
#define NTOK   (BLKT * NBLK)        // 4128
#define MROWS  (BATCH * NTOK)       // 16512
#define DMODEL 1024
#define QKVC   3072
#define WN     (DMODEL * DMODEL)    // 1M

// Scratch (allocation-free rule: __device__ globals)
__device__ float g_qkv[(size_t)MROWS * QKVC];
__device__ __nv_bfloat16 g_xh[(size_t)MROWS * DMODEL];
__device__ __nv_bfloat16 g_xl[(size_t)MROWS * DMODEL];
__device__ __nv_bfloat16 g_wh[(size_t)3 * WN];
__device__ __nv_bfloat16 g_wl[(size_t)3 * WN];
__device__ __half g_woh[(size_t)WN];
__device__ __half g_wol[(size_t)WN];
__device__ __half g_oh[(size_t)MROWS * DMODEL];   // attention output (fp16)

// ---------------------------------------------------------------------------
// Split kernels
// ---------------------------------------------------------------------------
__global__ void split_bf16(const float* __restrict__ in,
                           __nv_bfloat16* __restrict__ hi,
                           __nv_bfloat16* __restrict__ lo, int n)
{
    int i = (blockIdx.x * blockDim.x + threadIdx.x) * 4;
    if (i >= n) return;
    float4 v = *(const float4*)(in + i);
    __nv_bfloat16 h0 = __float2bfloat16(v.x), h1 = __float2bfloat16(v.y);
    __nv_bfloat16 h2 = __float2bfloat16(v.z), h3 = __float2bfloat16(v.w);
    *(__nv_bfloat162*)(hi + i)     = __nv_bfloat162(h0, h1);
    *(__nv_bfloat162*)(hi + i + 2) = __nv_bfloat162(h2, h3);
    *(__nv_bfloat162*)(lo + i) = __nv_bfloat162(
        __float2bfloat16(v.x - __bfloat162float(h0)),
        __float2bfloat16(v.y - __bfloat162float(h1)));
    *(__nv_bfloat162*)(lo + i + 2) = __nv_bfloat162(
        __float2bfloat16(v.z - __bfloat162float(h2)),
        __float2bfloat16(v.w - __bfloat162float(h3)));
}

__global__ void split_w3(const float* __restrict__ Wq, const float* __restrict__ Wk,
                         const float* __restrict__ Wv,
                         __nv_bfloat16* __restrict__ hi, __nv_bfloat16* __restrict__ lo)
{
    const int w = blockIdx.y;
    const float* src = (w == 0) ? Wq : (w == 1) ? Wk : Wv;
    size_t off = (size_t)w * WN;
    int i = (blockIdx.x * blockDim.x + threadIdx.x) * 4;
    if (i >= WN) return;
    float4 v = *(const float4*)(src + i);
    __nv_bfloat16 h0 = __float2bfloat16(v.x), h1 = __float2bfloat16(v.y);
    __nv_bfloat16 h2 = __float2bfloat16(v.z), h3 = __float2bfloat16(v.w);
    *(__nv_bfloat162*)(hi + off + i)     = __nv_bfloat162(h0, h1);
    *(__nv_bfloat162*)(hi + off + i + 2) = __nv_bfloat162(h2, h3);
    *(__nv_bfloat162*)(lo + off + i) = __nv_bfloat162(
        __float2bfloat16(v.x - __bfloat162float(h0)),
        __float2bfloat16(v.y - __bfloat162float(h1)));
    *(__nv_bfloat162*)(lo + off + i + 2) = __nv_bfloat162(
        __float2bfloat16(v.z - __bfloat162float(h2)),
        __float2bfloat16(v.w - __bfloat162float(h3)));
}

__global__ void split_fp16(const float* __restrict__ in,
                           __half* __restrict__ hi, __half* __restrict__ lo, int n)
{
    int i = (blockIdx.x * blockDim.x + threadIdx.x) * 4;
    if (i >= n) return;
    float4 v = *(const float4*)(in + i);
    __half h0 = __float2half(v.x), h1 = __float2half(v.y);
    __half h2 = __float2half(v.z), h3 = __float2half(v.w);
    *(__half2*)(hi + i)     = __half2(h0, h1);
    *(__half2*)(hi + i + 2) = __half2(h2, h3);
    *(__half2*)(lo + i) = __half2(__float2half(v.x - __half2float(h0)),
                                  __float2half(v.y - __half2float(h1)));
    *(__half2*)(lo + i + 2) = __half2(__float2half(v.z - __half2float(h2)),
                                      __float2half(v.w - __half2float(h3)));
}

// ---------------------------------------------------------------------------
// Tensor-core GEMM (NT): C[m,n] = sum_k A[m,k]*B[n,k] (+bias)
// TM=128, TN=256, BK=32, 8 warps of 64x64, mma.m16n8k16 + ldmatrix.x4.
// 3-stage cp.async pipeline; loads for chunk it+2 are interleaved into the
// MMA loop of chunk it; one __syncthreads per chunk.
// NPASS=3 (bf16): C = Ah*Bh + Ah*Bl + Al*Bh
// NPASS=2 (fp16): C = Ah*(Bh+Bl)
// ---------------------------------------------------------------------------
#define NSTG 3

__device__ __forceinline__ void cpa16(uint32_t dst, const void* src) {
    asm volatile("cp.async.cg.shared.global [%0], [%1], 16;\n" :: "r"(dst), "l"(src));
}
__device__ __forceinline__ void ldsm4(uint32_t* r, uint32_t addr) {
    asm volatile("ldmatrix.sync.aligned.m8n8.x4.shared.b16 {%0,%1,%2,%3}, [%4];"
                 : "=r"(r[0]), "=r"(r[1]), "=r"(r[2]), "=r"(r[3]) : "r"(addr));
}
__device__ __forceinline__ void mma_bf16(float* c, const uint32_t* a, const uint32_t* b) {
    asm volatile(
        "mma.sync.aligned.m16n8k16.row.col.f32.bf16.bf16.f32 "
        "{%0,%1,%2,%3}, {%4,%5,%6,%7}, {%8,%9}, {%0,%1,%2,%3};\n"
        : "+f"(c[0]), "+f"(c[1]), "+f"(c[2]), "+f"(c[3])
        : "r"(a[0]), "r"(a[1]), "r"(a[2]), "r"(a[3]), "r"(b[0]), "r"(b[1]));
}
__device__ __forceinline__ void mma_fp16(float* c, const uint32_t* a, const uint32_t* b) {
    asm volatile(
        "mma.sync.aligned.m16n8k16.row.col.f32.f16.f16.f32 "
        "{%0,%1,%2,%3}, {%4,%5,%6,%7}, {%8,%9}, {%0,%1,%2,%3};\n"
        : "+f"(c[0]), "+f"(c[1]), "+f"(c[2]), "+f"(c[3])
        : "r"(a[0]), "r"(a[1]), "r"(a[2]), "r"(a[3]), "r"(b[0]), "r"(b[1]));
}

template<typename T, int NPASS>
__global__ __launch_bounds__(256)
void gemm_tc(const T* __restrict__ Ahg, const T* __restrict__ Alg,
             const T* __restrict__ Bhg, const T* __restrict__ Blg,
             const float* __restrict__ bias,
             float* __restrict__ C, int K, int ldc)
{
    constexpr int APL   = (NPASS == 3) ? 2 : 1;
    constexpr int APB   = 10240;                        // 128 rows * 80B
    constexpr int BPB   = 20480;                        // 256 rows * 80B
    constexpr int BOFF  = APL * APB;
    constexpr int STGB  = APL * APB + 2 * BPB;

    extern __shared__ __align__(128) char smc[];
    const uint32_t sbase = (uint32_t)__cvta_generic_to_shared(smc);
    const int tid = threadIdx.x;
    const int warp = tid >> 5, lane = tid & 31;
    const int warp_m = warp & 1, warp_n = warp >> 1;
    const int g = lane >> 2, t = lane & 3;
    const int m0 = blockIdx.x << 7;
    const int n0 = blockIdx.y << 8;
    const int NCH = K >> 5;

    float acc[4][8][4];
#pragma unroll
    for (int i = 0; i < 4; ++i)
#pragma unroll
        for (int j = 0; j < 8; ++j)
#pragma unroll
            for (int r = 0; r < 4; ++r) acc[i][j][r] = 0.f;

    const int a_row = lane & 15;
    const int a_k16 = (lane >> 4) << 4;
    const int b_nt  = lane >> 4;
    const int b_row = lane & 7;
    const int b_k16 = ((lane >> 3) & 1) << 4;
    const uint32_t a_base = (uint32_t)((warp_m * 64 + a_row) * 80 + a_k16);
    const uint32_t b_base = (uint32_t)((warp_n * 64 + b_nt * 8 + b_row) * 80 + b_k16);

    // One load segment = 1/6 of a chunk's cp.async traffic.
    auto loadSeg = [&](int chunk, int seg) {
        const uint32_t s = sbase + (uint32_t)(chunk % NSTG) * STGB;
        const int k0 = chunk << 5;
        if (seg < 2) {
            int idx = tid + (seg << 8);
            int r = idx >> 2, c = idx & 3;
            uint32_t so = (uint32_t)(r * 80 + c * 16);
            size_t ga = (size_t)(m0 + r) * K + k0 + c * 8;
            cpa16(s + so, Ahg + ga);
            if (NPASS == 3) cpa16(s + APB + so, Alg + ga);
        } else {
            int idx = tid + ((seg - 2) << 8);
            int r = idx >> 2, c = idx & 3;
            uint32_t so = (uint32_t)(r * 80 + c * 16);
            size_t gb = (size_t)(n0 + r) * K + k0 + c * 8;
            cpa16(s + BOFF + so, Bhg + gb);
            cpa16(s + BOFF + BPB + so, Blg + gb);
        }
    };

    auto compute = [&](int st, int lchunk, bool doLoad) {
        const uint32_t s = sbase + (uint32_t)st * STGB;
        int seg = 0;
#pragma unroll
        for (int ks = 0; ks < 2; ++ks) {
            const uint32_t ko = (uint32_t)(ks * 32);
            uint32_t ah[4][4], al[4][4];
#pragma unroll
            for (int i = 0; i < 4; ++i) {
                ldsm4(ah[i], s + a_base + (uint32_t)(i * 1280) + ko);
                if (NPASS == 3)
                    ldsm4(al[i], s + APB + a_base + (uint32_t)(i * 1280) + ko);
            }
#pragma unroll
            for (int jp = 0; jp < 4; ++jp) {
                uint32_t bh[4], bl[4];
                ldsm4(bh, s + BOFF + b_base + (uint32_t)(jp * 1280) + ko);
                ldsm4(bl, s + BOFF + BPB + b_base + (uint32_t)(jp * 1280) + ko);
#pragma unroll
                for (int i = 0; i < 4; ++i)
#pragma unroll
                    for (int jj = 0; jj < 2; ++jj) {
                        float* cc = acc[i][jp * 2 + jj];
                        if (NPASS == 3) {
                            mma_bf16(cc, ah[i], &bh[jj * 2]);
                            mma_bf16(cc, ah[i], &bl[jj * 2]);
                            mma_bf16(cc, al[i], &bh[jj * 2]);
                        } else {
                            mma_fp16(cc, ah[i], &bh[jj * 2]);
                            mma_fp16(cc, ah[i], &bl[jj * 2]);
                        }
                    }
                if (doLoad && seg < 6) { loadSeg(lchunk, seg); ++seg; }
            }
        }
    };

    // Prologue: fully load chunks 0 and 1
#pragma unroll
    for (int sgi = 0; sgi < 6; ++sgi) loadSeg(0, sgi);
    asm volatile("cp.async.commit_group;\n");
#pragma unroll
    for (int sgi = 0; sgi < 6; ++sgi) loadSeg(1, sgi);
    asm volatile("cp.async.commit_group;\n");

    for (int it = 0; it < NCH; ++it) {
        asm volatile("cp.async.wait_group %0;\n" :: "n"(NSTG - 2));
        __syncthreads();
        compute(it % NSTG, it + 2, (it + 2) < NCH);
        asm volatile("cp.async.commit_group;\n");
    }

#pragma unroll
    for (int i = 0; i < 4; ++i) {
        int row0 = m0 + warp_m * 64 + i * 16 + g;
#pragma unroll
        for (int j = 0; j < 8; ++j) {
            int col = n0 + warp_n * 64 + j * 8 + 2 * t;
            float b0 = bias ? bias[col] : 0.f;
            float b1 = bias ? bias[col + 1] : 0.f;
            float2 v0 = {acc[i][j][0] + b0, acc[i][j][1] + b1};
            float2 v1 = {acc[i][j][2] + b0, acc[i][j][3] + b1};
            *(float2*)&C[(size_t)row0 * ldc + col] = v0;
            *(float2*)&C[(size_t)(row0 + 8) * ldc + col] = v1;
        }
    }
}

// ---------------------------------------------------------------------------
// Block-local attention; writes fp16 g_oh directly.
// ---------------------------------------------------------------------------
__global__ __launch_bounds__(256, 2)
void attn_local()
{
    const int h = blockIdx.x, nb = blockIdx.y, b = blockIdx.z;
    const int tid = threadIdx.x, warp = tid >> 5, lane = tid & 31;
    extern __shared__ float smf[];
    float* Ks = smf;
    float* Vs = Ks + BLKT * 68;
    float* Qs = Vs + BLKT * 68;
    float* Ps = Qs + 8 * 128;

    const size_t base = ((size_t)(b * NTOK + nb * BLKT)) * QKVC + h * DK;

    for (int f = tid; f < BLKT * 16; f += 256) {
        int r = f >> 4, c4 = (f & 15) << 2;
        *(float4*)&Ks[r * 68 + c4] =
            *(const float4*)&g_qkv[base + 1024 + (size_t)r * QKVC + c4];
        *(float4*)&Vs[r * 68 + c4] =
            *(const float4*)&g_qkv[base + 2048 + (size_t)r * QKVC + c4];
    }
    __syncthreads();

    const float scale = 0.125f;
    const int half = lane >> 4;
    const int dl = (lane & 15) << 2;
    float* Qw = Qs + warp * 128;
    float* Pw = Ps + warp * 264;

    for (int p = warp; p < 65; p += 8) {
        const int r0 = p * 2;
        const bool has1 = (r0 + 1) < BLKT;
        const int r1m = has1 ? r0 + 1 : r0;
        Qw[lane]      = g_qkv[base + (size_t)r0 * QKVC + lane];
        Qw[lane + 32] = g_qkv[base + (size_t)r0 * QKVC + lane + 32];
        Qw[64 + lane]      = g_qkv[base + (size_t)r1m * QKVC + lane];
        Qw[64 + lane + 32] = g_qkv[base + (size_t)r1m * QKVC + lane + 32];
        __syncwarp();

        float s0[5], s1[5];
#pragma unroll
        for (int jj = 0; jj < 5; ++jj) {
            const int j = lane + (jj << 5);
            float a0 = 0.f, a1 = 0.f;
            if (j < BLKT) {
                const float* kr = Ks + j * 68;
#pragma unroll
                for (int d4 = 0; d4 < 16; ++d4) {
                    float4 kk4 = *(const float4*)&kr[d4 << 2];
                    float4 q0  = *(const float4*)&Qw[d4 << 2];
                    float4 q1  = *(const float4*)&Qw[64 + (d4 << 2)];
                    a0 += kk4.x * q0.x + kk4.y * q0.y + kk4.z * q0.z + kk4.w * q0.w;
                    a1 += kk4.x * q1.x + kk4.y * q1.y + kk4.z * q1.z + kk4.w * q1.w;
                }
            }
            s0[jj] = (j < BLKT) ? a0 * scale : -CUDART_INF_F;
            s1[jj] = (j < BLKT) ? a1 * scale : -CUDART_INF_F;
        }

        float m0 = s0[0], m1 = s1[0];
#pragma unroll
        for (int jj = 1; jj < 5; ++jj) { m0 = fmaxf(m0, s0[jj]); m1 = fmaxf(m1, s1[jj]); }
#pragma unroll
        for (int o = 16; o > 0; o >>= 1) {
            m0 = fmaxf(m0, __shfl_xor_sync(0xffffffffu, m0, o));
            m1 = fmaxf(m1, __shfl_xor_sync(0xffffffffu, m1, o));
        }
        float e0[5], e1[5], sum0 = 0.f, sum1 = 0.f;
#pragma unroll
        for (int jj = 0; jj < 5; ++jj) {
            const int j = lane + (jj << 5);
            e0[jj] = (j < BLKT) ? __expf(s0[jj] - m0) : 0.f;
            e1[jj] = (j < BLKT) ? __expf(s1[jj] - m1) : 0.f;
            sum0 += e0[jj]; sum1 += e1[jj];
        }
#pragma unroll
        for (int o = 16; o > 0; o >>= 1) {
            sum0 += __shfl_xor_sync(0xffffffffu, sum0, o);
            sum1 += __shfl_xor_sync(0xffffffffu, sum1, o);
        }
        const float i0 = 1.f / sum0, i1 = 1.f / sum1;
#pragma unroll
        for (int jj = 0; jj < 5; ++jj) {
            const int j = lane + (jj << 5);
            if (j < BLKT) { Pw[j] = e0[jj] * i0; Pw[132 + j] = e1[jj] * i1; }
        }
        __syncwarp();

        float4 o0 = {0, 0, 0, 0}, o1 = {0, 0, 0, 0};
        const int kbase = half * 65;
        for (int tt = 0; tt < 65; ++tt) {
            const int key = kbase + tt;
            if (key < BLKT) {
                const float p0 = Pw[key], p1 = Pw[132 + key];
                float4 vv = *(const float4*)&Vs[key * 68 + dl];
                o0.x += p0 * vv.x; o0.y += p0 * vv.y; o0.z += p0 * vv.z; o0.w += p0 * vv.w;
                o1.x += p1 * vv.x; o1.y += p1 * vv.y; o1.z += p1 * vv.z; o1.w += p1 * vv.w;
            }
        }
        o0.x += __shfl_xor_sync(0xffffffffu, o0.x, 16);
        o0.y += __shfl_xor_sync(0xffffffffu, o0.y, 16);
        o0.z += __shfl_xor_sync(0xffffffffu, o0.z, 16);
        o0.w += __shfl_xor_sync(0xffffffffu, o0.w, 16);
        o1.x += __shfl_xor_sync(0xffffffffu, o1.x, 16);
        o1.y += __shfl_xor_sync(0xffffffffu, o1.y, 16);
        o1.z += __shfl_xor_sync(0xffffffffu, o1.z, 16);
        o1.w += __shfl_xor_sync(0xffffffffu, o1.w, 16);

        const size_t obase = ((size_t)(b * NTOK + nb * BLKT)) * DMODEL + h * DK;
        if (lane < 16) {
            __half2* d0 = (__half2*)&g_oh[obase + (size_t)r0 * DMODEL + dl];
            d0[0] = __floats2half2_rn(o0.x, o0.y);
            d0[1] = __floats2half2_rn(o0.z, o0.w);
            if (has1) {
                __half2* d1 = (__half2*)&g_oh[obase + (size_t)(r0 + 1) * DMODEL + dl];
                d1[0] = __floats2half2_rn(o1.x, o1.y);
                d1[1] = __floats2half2_rn(o1.z, o1.w);
            }
        }
        __syncwarp();
    }
}

// ---------------------------------------------------------------------------
// Global (block-leader) attention: fp16 RMW on g_oh leader rows.
// ---------------------------------------------------------------------------
__global__ void attn_global()
{
    const int b = blockIdx.x >> 4, h = blockIdx.x & 15;
    const int lane = threadIdx.x;
    __shared__ float kg[32 * 65], vg[32 * 65], qg[32 * 65], pg[32 * 33];

    const size_t rb = ((size_t)(b * NTOK + lane * BLKT)) * QKVC + h * DK;
    for (int d = 0; d < 64; ++d) {
        qg[lane * 65 + d] = g_qkv[rb + d];
        kg[lane * 65 + d] = g_qkv[rb + 1024 + d];
        vg[lane * 65 + d] = g_qkv[rb + 2048 + d];
    }
    __syncwarp();

    for (int kk = 0; kk < 32; ++kk) {
        float a = 0.f;
        for (int d = 0; d < 64; ++d) a += qg[lane * 65 + d] * kg[kk * 65 + d];
        pg[lane * 33 + kk] = a * 0.125f;
    }
    float mx = -CUDART_INF_F;
    for (int kk = 0; kk < 32; ++kk) mx = fmaxf(mx, pg[lane * 33 + kk]);
    float sum = 0.f;
    for (int kk = 0; kk < 32; ++kk) {
        float e = __expf(pg[lane * 33 + kk] - mx);
        pg[lane * 33 + kk] = e;
        sum += e;
    }
    const float inv = 1.f / sum;
    __syncwarp();

    const size_t ob = ((size_t)(b * NTOK + lane * BLKT)) * DMODEL + h * DK;
    for (int d = 0; d < 64; ++d) {
        float acc = 0.f;
        for (int kk = 0; kk < 32; ++kk)
            acc += pg[lane * 33 + kk] * vg[kk * 65 + d];
        float cur = __half2float(g_oh[ob + d]);
        g_oh[ob + d] = __float2half(cur + acc * inv);
    }
}

// ---------------------------------------------------------------------------
extern "C" void kernel_launch(void* const* d_in, const int* in_sizes, int n_in,
                              void* d_out, int out_size)
{
    const float* x  = (const float*)d_in[0];
    const float* Wq = (const float*)d_in[1];
    const float* Wk = (const float*)d_in[2];
    const float* Wv = (const float*)d_in[3];
    const float* Wo = (const float*)d_in[4];
    const float* bo = (const float*)d_in[5];
    float* out = (float*)d_out;

    float* qkv = nullptr;
    __nv_bfloat16 *xh, *xl, *wh, *wl;
    __half *woh, *wol, *oh;
    cudaGetSymbolAddress((void**)&qkv, g_qkv);
    cudaGetSymbolAddress((void**)&xh, g_xh);
    cudaGetSymbolAddress((void**)&xl, g_xl);
    cudaGetSymbolAddress((void**)&wh, g_wh);
    cudaGetSymbolAddress((void**)&wl, g_wl);
    cudaGetSymbolAddress((void**)&woh, g_woh);
    cudaGetSymbolAddress((void**)&wol, g_wol);
    cudaGetSymbolAddress((void**)&oh, g_oh);

    // 0) precision splits
    split_bf16<<<(MROWS * DMODEL / 4 + 255) / 256, 256>>>(x, xh, xl, MROWS * DMODEL);
    split_w3<<<dim3(WN / 4 / 256, 3), 256>>>(Wq, Wk, Wv, wh, wl);
    split_fp16<<<(WN / 4 + 255) / 256, 256>>>(Wo, woh, wol, WN);

    // 1) QKV projection (bf16x3, TN=256)
    constexpr int GS3 = NSTG * (2 * 10240 + 2 * 20480);   // 184320
    constexpr int GS2 = NSTG * (1 * 10240 + 2 * 20480);   // 153600
    auto* f3 = gemm_tc<__nv_bfloat16, 3>;
    auto* f2 = gemm_tc<__half, 2>;
    cudaFuncSetAttribute(f3, cudaFuncAttributeMaxDynamicSharedMemorySize, GS3);
    cudaFuncSetAttribute(f2, cudaFuncAttributeMaxDynamicSharedMemorySize, GS2);
    gemm_tc<__nv_bfloat16, 3><<<dim3(MROWS / 128, QKVC / 256), 256, GS3>>>(
        xh, xl, wh, wl, nullptr, qkv, DMODEL, QKVC);

    // 2) block-local attention -> g_oh (fp16)
    const size_t smem = (2 * BLKT * 68 + 8 * 128 + 8 * 264) * sizeof(float);
    cudaFuncSetAttribute(attn_local,
                         cudaFuncAttributeMaxDynamicSharedMemorySize, (int)smem);
    attn_local<<<dim3(HEADS, NBLK, BATCH), 256, smem>>>();

    // 3) global leader attention (fp16 RMW into g_oh)
    attn_global<<<BATCH * HEADS, 32>>>();

    // 4) out = g_oh @ (Woh+Wol)^T + bo   (fp16 2-pass, TN=256)
    gemm_tc<__half, 2><<<dim3(MROWS / 128, DMODEL / 256), 256, GS2>>>(
        oh, nullptr, woh, wol, bo, out, DMODEL, DMODEL);
}

// round 10
// speedup vs baseline: 2.4560x; 1.0763x over previous
#include <cuda_runtime.h>
#include <cuda_bf16.h>
#include <cuda_fp16.h>
#include <math_constants.h>
#include <cstdint>
#include <cstddef>

#define HEADS  16
#define DK     64
#define BLKT   129
#define NBLK   32
#define BATCH  4
#define NTOK   (BLKT * NBLK)        // 4128
#define MROWS  (BATCH * NTOK)       // 16512
#define DMODEL 1024
#define QKVC   3072
#define WN     (DMODEL * DMODEL)    // 1M

// Scratch (allocation-free rule: __device__ globals)
__device__ float g_qkv[(size_t)MROWS * QKVC];
__device__ __nv_bfloat16 g_xh[(size_t)MROWS * DMODEL];
__device__ __nv_bfloat16 g_xl[(size_t)MROWS * DMODEL];
__device__ __nv_bfloat16 g_wh[(size_t)3 * WN];
__device__ __nv_bfloat16 g_wl[(size_t)3 * WN];
__device__ __half g_woh[(size_t)WN];
__device__ __half g_wol[(size_t)WN];
__device__ __half g_oh[(size_t)MROWS * DMODEL];   // attention output (fp16)

// ---------------------------------------------------------------------------
// Split kernels
// ---------------------------------------------------------------------------
__global__ void split_bf16(const float* __restrict__ in,
                           __nv_bfloat16* __restrict__ hi,
                           __nv_bfloat16* __restrict__ lo, int n)
{
    int i = (blockIdx.x * blockDim.x + threadIdx.x) * 4;
    if (i >= n) return;
    float4 v = *(const float4*)(in + i);
    __nv_bfloat16 h0 = __float2bfloat16(v.x), h1 = __float2bfloat16(v.y);
    __nv_bfloat16 h2 = __float2bfloat16(v.z), h3 = __float2bfloat16(v.w);
    *(__nv_bfloat162*)(hi + i)     = __nv_bfloat162(h0, h1);
    *(__nv_bfloat162*)(hi + i + 2) = __nv_bfloat162(h2, h3);
    *(__nv_bfloat162*)(lo + i) = __nv_bfloat162(
        __float2bfloat16(v.x - __bfloat162float(h0)),
        __float2bfloat16(v.y - __bfloat162float(h1)));
    *(__nv_bfloat162*)(lo + i + 2) = __nv_bfloat162(
        __float2bfloat16(v.z - __bfloat162float(h2)),
        __float2bfloat16(v.w - __bfloat162float(h3)));
}

__global__ void split_w3(const float* __restrict__ Wq, const float* __restrict__ Wk,
                         const float* __restrict__ Wv,
                         __nv_bfloat16* __restrict__ hi, __nv_bfloat16* __restrict__ lo)
{
    const int w = blockIdx.y;
    const float* src = (w == 0) ? Wq : (w == 1) ? Wk : Wv;
    size_t off = (size_t)w * WN;
    int i = (blockIdx.x * blockDim.x + threadIdx.x) * 4;
    if (i >= WN) return;
    float4 v = *(const float4*)(src + i);
    __nv_bfloat16 h0 = __float2bfloat16(v.x), h1 = __float2bfloat16(v.y);
    __nv_bfloat16 h2 = __float2bfloat16(v.z), h3 = __float2bfloat16(v.w);
    *(__nv_bfloat162*)(hi + off + i)     = __nv_bfloat162(h0, h1);
    *(__nv_bfloat162*)(hi + off + i + 2) = __nv_bfloat162(h2, h3);
    *(__nv_bfloat162*)(lo + off + i) = __nv_bfloat162(
        __float2bfloat16(v.x - __bfloat162float(h0)),
        __float2bfloat16(v.y - __bfloat162float(h1)));
    *(__nv_bfloat162*)(lo + off + i + 2) = __nv_bfloat162(
        __float2bfloat16(v.z - __bfloat162float(h2)),
        __float2bfloat16(v.w - __bfloat162float(h3)));
}

__global__ void split_fp16(const float* __restrict__ in,
                           __half* __restrict__ hi, __half* __restrict__ lo, int n)
{
    int i = (blockIdx.x * blockDim.x + threadIdx.x) * 4;
    if (i >= n) return;
    float4 v = *(const float4*)(in + i);
    __half h0 = __float2half(v.x), h1 = __float2half(v.y);
    __half h2 = __float2half(v.z), h3 = __float2half(v.w);
    *(__half2*)(hi + i)     = __half2(h0, h1);
    *(__half2*)(hi + i + 2) = __half2(h2, h3);
    *(__half2*)(lo + i) = __half2(__float2half(v.x - __half2float(h0)),
                                  __float2half(v.y - __half2float(h1)));
    *(__half2*)(lo + i + 2) = __half2(__float2half(v.z - __half2float(h2)),
                                      __float2half(v.w - __half2float(h3)));
}

// ---------------------------------------------------------------------------
// Tensor-core GEMM (NT): C[m,n] = sum_k A[m,k]*B[n,k] (+bias)
// TM=128, TN=128, BK=32, 8 warps (4m x 2n grid, 32x64 warp tiles),
// mma.m16n8k16 + ldmatrix.x4, 2-stage cp.async, 2 CTAs/SM.
// Loads for chunk it+1 interleave into the first half of compute(it).
// NPASS=3 (bf16): C = Ah*Bh + Ah*Bl + Al*Bh
// NPASS=2 (fp16): C = Ah*(Bh+Bl)
// ---------------------------------------------------------------------------
__device__ __forceinline__ void cpa16(uint32_t dst, const void* src) {
    asm volatile("cp.async.cg.shared.global [%0], [%1], 16;\n" :: "r"(dst), "l"(src));
}
__device__ __forceinline__ void ldsm4(uint32_t* r, uint32_t addr) {
    asm volatile("ldmatrix.sync.aligned.m8n8.x4.shared.b16 {%0,%1,%2,%3}, [%4];"
                 : "=r"(r[0]), "=r"(r[1]), "=r"(r[2]), "=r"(r[3]) : "r"(addr));
}
__device__ __forceinline__ void mma_bf16(float* c, const uint32_t* a, const uint32_t* b) {
    asm volatile(
        "mma.sync.aligned.m16n8k16.row.col.f32.bf16.bf16.f32 "
        "{%0,%1,%2,%3}, {%4,%5,%6,%7}, {%8,%9}, {%0,%1,%2,%3};\n"
        : "+f"(c[0]), "+f"(c[1]), "+f"(c[2]), "+f"(c[3])
        : "r"(a[0]), "r"(a[1]), "r"(a[2]), "r"(a[3]), "r"(b[0]), "r"(b[1]));
}
__device__ __forceinline__ void mma_fp16(float* c, const uint32_t* a, const uint32_t* b) {
    asm volatile(
        "mma.sync.aligned.m16n8k16.row.col.f32.f16.f16.f32 "
        "{%0,%1,%2,%3}, {%4,%5,%6,%7}, {%8,%9}, {%0,%1,%2,%3};\n"
        : "+f"(c[0]), "+f"(c[1]), "+f"(c[2]), "+f"(c[3])
        : "r"(a[0]), "r"(a[1]), "r"(a[2]), "r"(a[3]), "r"(b[0]), "r"(b[1]));
}

template<typename T, int NPASS>
__global__ __launch_bounds__(256, 2)
void gemm_tc(const T* __restrict__ Ahg, const T* __restrict__ Alg,
             const T* __restrict__ Bhg, const T* __restrict__ Blg,
             const float* __restrict__ bias,
             float* __restrict__ C, int K, int ldc)
{
    constexpr int APL  = (NPASS == 3) ? 2 : 1;         // A planes
    constexpr int APB  = 10240;                         // 128 rows * 80B
    constexpr int BPB  = 10240;                         // 128 rows * 80B
    constexpr int BOFF = APL * APB;
    constexpr int STGB = APL * APB + 2 * BPB;

    extern __shared__ __align__(128) char smc[];
    const uint32_t sbase = (uint32_t)__cvta_generic_to_shared(smc);
    const int tid = threadIdx.x;
    const int warp = tid >> 5, lane = tid & 31;
    const int warp_m = warp >> 1, warp_n = warp & 1;    // 4m x 2n
    const int g = lane >> 2, t = lane & 3;
    const int m0 = blockIdx.x << 7;
    const int n0 = blockIdx.y << 7;
    const int NCH = K >> 5;

    float acc[2][8][4];
#pragma unroll
    for (int i = 0; i < 2; ++i)
#pragma unroll
        for (int j = 0; j < 8; ++j)
#pragma unroll
            for (int r = 0; r < 4; ++r) acc[i][j][r] = 0.f;

    const int a_row = lane & 15;
    const int a_k16 = (lane >> 4) << 4;
    const int b_nt  = lane >> 4;
    const int b_row = lane & 7;
    const int b_k16 = ((lane >> 3) & 1) << 4;
    const uint32_t a_base = (uint32_t)((warp_m * 32 + a_row) * 80 + a_k16);
    const uint32_t b_base = (uint32_t)((warp_n * 64 + b_nt * 8 + b_row) * 80 + b_k16);

    // One segment = 1/4 of a chunk's cp.async traffic (1-2 cpa16/thread).
    auto loadSeg = [&](int chunk, int seg) {
        const uint32_t s = sbase + (uint32_t)(chunk & 1) * STGB;
        const int k0 = chunk << 5;
        int idx = tid + ((seg & 1) << 8);
        int r = idx >> 2, c = idx & 3;
        uint32_t so = (uint32_t)(r * 80 + c * 16);
        if (seg < 2) {
            size_t ga = (size_t)(m0 + r) * K + k0 + c * 8;
            cpa16(s + so, Ahg + ga);
            if (NPASS == 3) cpa16(s + APB + so, Alg + ga);
        } else {
            size_t gb = (size_t)(n0 + r) * K + k0 + c * 8;
            cpa16(s + BOFF + so, Bhg + gb);
            cpa16(s + BOFF + BPB + so, Blg + gb);
        }
    };

    auto compute = [&](int st, int lchunk, bool doLoad) {
        const uint32_t s = sbase + (uint32_t)st * STGB;
        int seg = 0;
#pragma unroll
        for (int ks = 0; ks < 2; ++ks) {
            const uint32_t ko = (uint32_t)(ks * 32);
            uint32_t ah[2][4], al[2][4];
#pragma unroll
            for (int i = 0; i < 2; ++i) {
                ldsm4(ah[i], s + a_base + (uint32_t)(i * 1280) + ko);
                if (NPASS == 3)
                    ldsm4(al[i], s + APB + a_base + (uint32_t)(i * 1280) + ko);
            }
#pragma unroll
            for (int jp = 0; jp < 4; ++jp) {
                uint32_t bh[4], bl[4];
                ldsm4(bh, s + BOFF + b_base + (uint32_t)(jp * 1280) + ko);
                ldsm4(bl, s + BOFF + BPB + b_base + (uint32_t)(jp * 1280) + ko);
#pragma unroll
                for (int i = 0; i < 2; ++i)
#pragma unroll
                    for (int jj = 0; jj < 2; ++jj) {
                        float* cc = acc[i][jp * 2 + jj];
                        if (NPASS == 3) {
                            mma_bf16(cc, ah[i], &bh[jj * 2]);
                            mma_bf16(cc, ah[i], &bl[jj * 2]);
                            mma_bf16(cc, al[i], &bh[jj * 2]);
                        } else {
                            mma_fp16(cc, ah[i], &bh[jj * 2]);
                            mma_fp16(cc, ah[i], &bl[jj * 2]);
                        }
                    }
                if (doLoad && seg < 4) { loadSeg(lchunk, seg); ++seg; }
            }
        }
    };

    // Prologue: load chunk 0
#pragma unroll
    for (int sgi = 0; sgi < 4; ++sgi) loadSeg(0, sgi);
    asm volatile("cp.async.commit_group;\n");

    for (int it = 0; it < NCH; ++it) {
        asm volatile("cp.async.wait_group 0;\n");
        __syncthreads();
        compute(it & 1, it + 1, (it + 1) < NCH);
        asm volatile("cp.async.commit_group;\n");
    }

#pragma unroll
    for (int i = 0; i < 2; ++i) {
        int row0 = m0 + warp_m * 32 + i * 16 + g;
#pragma unroll
        for (int j = 0; j < 8; ++j) {
            int col = n0 + warp_n * 64 + j * 8 + 2 * t;
            float b0 = bias ? bias[col] : 0.f;
            float b1 = bias ? bias[col + 1] : 0.f;
            float2 v0 = {acc[i][j][0] + b0, acc[i][j][1] + b1};
            float2 v1 = {acc[i][j][2] + b0, acc[i][j][3] + b1};
            *(float2*)&C[(size_t)row0 * ldc + col] = v0;
            *(float2*)&C[(size_t)(row0 + 8) * ldc + col] = v1;
        }
    }
}

// ---------------------------------------------------------------------------
// Block-local attention; writes fp16 g_oh directly. (known-good)
// ---------------------------------------------------------------------------
__global__ __launch_bounds__(256, 2)
void attn_local()
{
    const int h = blockIdx.x, nb = blockIdx.y, b = blockIdx.z;
    const int tid = threadIdx.x, warp = tid >> 5, lane = tid & 31;
    extern __shared__ float smf[];
    float* Ks = smf;
    float* Vs = Ks + BLKT * 68;
    float* Qs = Vs + BLKT * 68;
    float* Ps = Qs + 8 * 128;

    const size_t base = ((size_t)(b * NTOK + nb * BLKT)) * QKVC + h * DK;

    for (int f = tid; f < BLKT * 16; f += 256) {
        int r = f >> 4, c4 = (f & 15) << 2;
        *(float4*)&Ks[r * 68 + c4] =
            *(const float4*)&g_qkv[base + 1024 + (size_t)r * QKVC + c4];
        *(float4*)&Vs[r * 68 + c4] =
            *(const float4*)&g_qkv[base + 2048 + (size_t)r * QKVC + c4];
    }
    __syncthreads();

    const float scale = 0.125f;
    const int half = lane >> 4;
    const int dl = (lane & 15) << 2;
    float* Qw = Qs + warp * 128;
    float* Pw = Ps + warp * 264;

    for (int p = warp; p < 65; p += 8) {
        const int r0 = p * 2;
        const bool has1 = (r0 + 1) < BLKT;
        const int r1m = has1 ? r0 + 1 : r0;
        Qw[lane]      = g_qkv[base + (size_t)r0 * QKVC + lane];
        Qw[lane + 32] = g_qkv[base + (size_t)r0 * QKVC + lane + 32];
        Qw[64 + lane]      = g_qkv[base + (size_t)r1m * QKVC + lane];
        Qw[64 + lane + 32] = g_qkv[base + (size_t)r1m * QKVC + lane + 32];
        __syncwarp();

        float s0[5], s1[5];
#pragma unroll
        for (int jj = 0; jj < 5; ++jj) {
            const int j = lane + (jj << 5);
            float a0 = 0.f, a1 = 0.f;
            if (j < BLKT) {
                const float* kr = Ks + j * 68;
#pragma unroll
                for (int d4 = 0; d4 < 16; ++d4) {
                    float4 kk4 = *(const float4*)&kr[d4 << 2];
                    float4 q0  = *(const float4*)&Qw[d4 << 2];
                    float4 q1  = *(const float4*)&Qw[64 + (d4 << 2)];
                    a0 += kk4.x * q0.x + kk4.y * q0.y + kk4.z * q0.z + kk4.w * q0.w;
                    a1 += kk4.x * q1.x + kk4.y * q1.y + kk4.z * q1.z + kk4.w * q1.w;
                }
            }
            s0[jj] = (j < BLKT) ? a0 * scale : -CUDART_INF_F;
            s1[jj] = (j < BLKT) ? a1 * scale : -CUDART_INF_F;
        }

        float m0 = s0[0], m1 = s1[0];
#pragma unroll
        for (int jj = 1; jj < 5; ++jj) { m0 = fmaxf(m0, s0[jj]); m1 = fmaxf(m1, s1[jj]); }
#pragma unroll
        for (int o = 16; o > 0; o >>= 1) {
            m0 = fmaxf(m0, __shfl_xor_sync(0xffffffffu, m0, o));
            m1 = fmaxf(m1, __shfl_xor_sync(0xffffffffu, m1, o));
        }
        float e0[5], e1[5], sum0 = 0.f, sum1 = 0.f;
#pragma unroll
        for (int jj = 0; jj < 5; ++jj) {
            const int j = lane + (jj << 5);
            e0[jj] = (j < BLKT) ? __expf(s0[jj] - m0) : 0.f;
            e1[jj] = (j < BLKT) ? __expf(s1[jj] - m1) : 0.f;
            sum0 += e0[jj]; sum1 += e1[jj];
        }
#pragma unroll
        for (int o = 16; o > 0; o >>= 1) {
            sum0 += __shfl_xor_sync(0xffffffffu, sum0, o);
            sum1 += __shfl_xor_sync(0xffffffffu, sum1, o);
        }
        const float i0 = 1.f / sum0, i1 = 1.f / sum1;
#pragma unroll
        for (int jj = 0; jj < 5; ++jj) {
            const int j = lane + (jj << 5);
            if (j < BLKT) { Pw[j] = e0[jj] * i0; Pw[132 + j] = e1[jj] * i1; }
        }
        __syncwarp();

        float4 o0 = {0, 0, 0, 0}, o1 = {0, 0, 0, 0};
        const int kbase = half * 65;
        for (int tt = 0; tt < 65; ++tt) {
            const int key = kbase + tt;
            if (key < BLKT) {
                const float p0 = Pw[key], p1 = Pw[132 + key];
                float4 vv = *(const float4*)&Vs[key * 68 + dl];
                o0.x += p0 * vv.x; o0.y += p0 * vv.y; o0.z += p0 * vv.z; o0.w += p0 * vv.w;
                o1.x += p1 * vv.x; o1.y += p1 * vv.y; o1.z += p1 * vv.z; o1.w += p1 * vv.w;
            }
        }
        o0.x += __shfl_xor_sync(0xffffffffu, o0.x, 16);
        o0.y += __shfl_xor_sync(0xffffffffu, o0.y, 16);
        o0.z += __shfl_xor_sync(0xffffffffu, o0.z, 16);
        o0.w += __shfl_xor_sync(0xffffffffu, o0.w, 16);
        o1.x += __shfl_xor_sync(0xffffffffu, o1.x, 16);
        o1.y += __shfl_xor_sync(0xffffffffu, o1.y, 16);
        o1.z += __shfl_xor_sync(0xffffffffu, o1.z, 16);
        o1.w += __shfl_xor_sync(0xffffffffu, o1.w, 16);

        const size_t obase = ((size_t)(b * NTOK + nb * BLKT)) * DMODEL + h * DK;
        if (lane < 16) {
            __half2* d0 = (__half2*)&g_oh[obase + (size_t)r0 * DMODEL + dl];
            d0[0] = __floats2half2_rn(o0.x, o0.y);
            d0[1] = __floats2half2_rn(o0.z, o0.w);
            if (has1) {
                __half2* d1 = (__half2*)&g_oh[obase + (size_t)(r0 + 1) * DMODEL + dl];
                d1[0] = __floats2half2_rn(o1.x, o1.y);
                d1[1] = __floats2half2_rn(o1.z, o1.w);
            }
        }
        __syncwarp();
    }
}

// ---------------------------------------------------------------------------
// Global (block-leader) attention: fp16 RMW on g_oh leader rows.
// ---------------------------------------------------------------------------
__global__ void attn_global()
{
    const int b = blockIdx.x >> 4, h = blockIdx.x & 15;
    const int lane = threadIdx.x;
    __shared__ float kg[32 * 65], vg[32 * 65], qg[32 * 65], pg[32 * 33];

    const size_t rb = ((size_t)(b * NTOK + lane * BLKT)) * QKVC + h * DK;
    for (int d = 0; d < 64; ++d) {
        qg[lane * 65 + d] = g_qkv[rb + d];
        kg[lane * 65 + d] = g_qkv[rb + 1024 + d];
        vg[lane * 65 + d] = g_qkv[rb + 2048 + d];
    }
    __syncwarp();

    for (int kk = 0; kk < 32; ++kk) {
        float a = 0.f;
        for (int d = 0; d < 64; ++d) a += qg[lane * 65 + d] * kg[kk * 65 + d];
        pg[lane * 33 + kk] = a * 0.125f;
    }
    float mx = -CUDART_INF_F;
    for (int kk = 0; kk < 32; ++kk) mx = fmaxf(mx, pg[lane * 33 + kk]);
    float sum = 0.f;
    for (int kk = 0; kk < 32; ++kk) {
        float e = __expf(pg[lane * 33 + kk] - mx);
        pg[lane * 33 + kk] = e;
        sum += e;
    }
    const float inv = 1.f / sum;
    __syncwarp();

    const size_t ob = ((size_t)(b * NTOK + lane * BLKT)) * DMODEL + h * DK;
    for (int d = 0; d < 64; ++d) {
        float acc = 0.f;
        for (int kk = 0; kk < 32; ++kk)
            acc += pg[lane * 33 + kk] * vg[kk * 65 + d];
        float cur = __half2float(g_oh[ob + d]);
        g_oh[ob + d] = __float2half(cur + acc * inv);
    }
}

// ---------------------------------------------------------------------------
extern "C" void kernel_launch(void* const* d_in, const int* in_sizes, int n_in,
                              void* d_out, int out_size)
{
    const float* x  = (const float*)d_in[0];
    const float* Wq = (const float*)d_in[1];
    const float* Wk = (const float*)d_in[2];
    const float* Wv = (const float*)d_in[3];
    const float* Wo = (const float*)d_in[4];
    const float* bo = (const float*)d_in[5];
    float* out = (float*)d_out;

    float* qkv = nullptr;
    __nv_bfloat16 *xh, *xl, *wh, *wl;
    __half *woh, *wol, *oh;
    cudaGetSymbolAddress((void**)&qkv, g_qkv);
    cudaGetSymbolAddress((void**)&xh, g_xh);
    cudaGetSymbolAddress((void**)&xl, g_xl);
    cudaGetSymbolAddress((void**)&wh, g_wh);
    cudaGetSymbolAddress((void**)&wl, g_wl);
    cudaGetSymbolAddress((void**)&woh, g_woh);
    cudaGetSymbolAddress((void**)&wol, g_wol);
    cudaGetSymbolAddress((void**)&oh, g_oh);

    // 0) precision splits
    split_bf16<<<(MROWS * DMODEL / 4 + 255) / 256, 256>>>(x, xh, xl, MROWS * DMODEL);
    split_w3<<<dim3(WN / 4 / 256, 3), 256>>>(Wq, Wk, Wv, wh, wl);
    split_fp16<<<(WN / 4 + 255) / 256, 256>>>(Wo, woh, wol, WN);

    // 1) QKV projection (bf16x3, TN=128, 2 CTAs/SM)
    constexpr int GS3 = 2 * (2 * 10240 + 2 * 10240);   // 81920
    constexpr int GS2 = 2 * (1 * 10240 + 2 * 10240);   // 61440
    auto* f3 = gemm_tc<__nv_bfloat16, 3>;
    auto* f2 = gemm_tc<__half, 2>;
    cudaFuncSetAttribute(f3, cudaFuncAttributeMaxDynamicSharedMemorySize, GS3);
    cudaFuncSetAttribute(f2, cudaFuncAttributeMaxDynamicSharedMemorySize, GS2);
    gemm_tc<__nv_bfloat16, 3><<<dim3(MROWS / 128, QKVC / 128), 256, GS3>>>(
        xh, xl, wh, wl, nullptr, qkv, DMODEL, QKVC);

    // 2) block-local attention -> g_oh (fp16)
    const size_t smem = (2 * BLKT * 68 + 8 * 128 + 8 * 264) * sizeof(float);
    cudaFuncSetAttribute(attn_local,
                         cudaFuncAttributeMaxDynamicSharedMemorySize, (int)smem);
    attn_local<<<dim3(HEADS, NBLK, BATCH), 256, smem>>>();

    // 3) global leader attention (fp16 RMW into g_oh)
    attn_global<<<BATCH * HEADS, 32>>>();

    // 4) out = g_oh @ (Woh+Wol)^T + bo   (fp16 2-pass, TN=128, 2 CTAs/SM)
    gemm_tc<__half, 2><<<dim3(MROWS / 128, DMODEL / 128), 256, GS2>>>(
        oh, nullptr, woh, wol, bo, out, DMODEL, DMODEL);
}

// round 11
// speedup vs baseline: 3.2971x; 1.3425x over previous
#include <cuda_runtime.h>
#include <cuda_bf16.h>
#include <cuda_fp16.h>
#include <math_constants.h>
#include <cstdint>
#include <cstddef>

#define HEADS  16
#define DK     64
#define BLKT   129
#define NBLK   32
#define BATCH  4
#define NTOK   (BLKT * NBLK)        // 4128
#define MROWS  (BATCH * NTOK)       // 16512
#define DMODEL 1024
#define QKVC   3072
#define WN     (DMODEL * DMODEL)    // 1M

// Scratch (allocation-free rule: __device__ globals)
__device__ float g_qkv[(size_t)MROWS * QKVC];
__device__ __nv_bfloat16 g_xh[(size_t)MROWS * DMODEL];
__device__ __nv_bfloat16 g_xl[(size_t)MROWS * DMODEL];
__device__ __nv_bfloat16 g_wh[(size_t)3 * WN];
__device__ __nv_bfloat16 g_wl[(size_t)3 * WN];
__device__ __half g_woh[(size_t)WN];
__device__ __half g_wol[(size_t)WN];
__device__ __half g_oh[(size_t)MROWS * DMODEL];   // attention output (fp16)

// ---------------------------------------------------------------------------
// Split kernels
// ---------------------------------------------------------------------------
__global__ void split_bf16(const float* __restrict__ in,
                           __nv_bfloat16* __restrict__ hi,
                           __nv_bfloat16* __restrict__ lo, int n)
{
    int i = (blockIdx.x * blockDim.x + threadIdx.x) * 4;
    if (i >= n) return;
    float4 v = *(const float4*)(in + i);
    __nv_bfloat16 h0 = __float2bfloat16(v.x), h1 = __float2bfloat16(v.y);
    __nv_bfloat16 h2 = __float2bfloat16(v.z), h3 = __float2bfloat16(v.w);
    *(__nv_bfloat162*)(hi + i)     = __nv_bfloat162(h0, h1);
    *(__nv_bfloat162*)(hi + i + 2) = __nv_bfloat162(h2, h3);
    *(__nv_bfloat162*)(lo + i) = __nv_bfloat162(
        __float2bfloat16(v.x - __bfloat162float(h0)),
        __float2bfloat16(v.y - __bfloat162float(h1)));
    *(__nv_bfloat162*)(lo + i + 2) = __nv_bfloat162(
        __float2bfloat16(v.z - __bfloat162float(h2)),
        __float2bfloat16(v.w - __bfloat162float(h3)));
}

__global__ void split_w3(const float* __restrict__ Wq, const float* __restrict__ Wk,
                         const float* __restrict__ Wv,
                         __nv_bfloat16* __restrict__ hi, __nv_bfloat16* __restrict__ lo)
{
    const int w = blockIdx.y;
    const float* src = (w == 0) ? Wq : (w == 1) ? Wk : Wv;
    size_t off = (size_t)w * WN;
    int i = (blockIdx.x * blockDim.x + threadIdx.x) * 4;
    if (i >= WN) return;
    float4 v = *(const float4*)(src + i);
    __nv_bfloat16 h0 = __float2bfloat16(v.x), h1 = __float2bfloat16(v.y);
    __nv_bfloat16 h2 = __float2bfloat16(v.z), h3 = __float2bfloat16(v.w);
    *(__nv_bfloat162*)(hi + off + i)     = __nv_bfloat162(h0, h1);
    *(__nv_bfloat162*)(hi + off + i + 2) = __nv_bfloat162(h2, h3);
    *(__nv_bfloat162*)(lo + off + i) = __nv_bfloat162(
        __float2bfloat16(v.x - __bfloat162float(h0)),
        __float2bfloat16(v.y - __bfloat162float(h1)));
    *(__nv_bfloat162*)(lo + off + i + 2) = __nv_bfloat162(
        __float2bfloat16(v.z - __bfloat162float(h2)),
        __float2bfloat16(v.w - __bfloat162float(h3)));
}

__global__ void split_fp16(const float* __restrict__ in,
                           __half* __restrict__ hi, __half* __restrict__ lo, int n)
{
    int i = (blockIdx.x * blockDim.x + threadIdx.x) * 4;
    if (i >= n) return;
    float4 v = *(const float4*)(in + i);
    __half h0 = __float2half(v.x), h1 = __float2half(v.y);
    __half h2 = __float2half(v.z), h3 = __float2half(v.w);
    *(__half2*)(hi + i)     = __half2(h0, h1);
    *(__half2*)(hi + i + 2) = __half2(h2, h3);
    *(__half2*)(lo + i) = __half2(__float2half(v.x - __half2float(h0)),
                                  __float2half(v.y - __half2float(h1)));
    *(__half2*)(lo + i + 2) = __half2(__float2half(v.z - __half2float(h2)),
                                      __float2half(v.w - __half2float(h3)));
}

// ---------------------------------------------------------------------------
// MMA / ldmatrix helpers
// ---------------------------------------------------------------------------
__device__ __forceinline__ void cpa16(uint32_t dst, const void* src) {
    asm volatile("cp.async.cg.shared.global [%0], [%1], 16;\n" :: "r"(dst), "l"(src));
}
__device__ __forceinline__ void ldsm4(uint32_t* r, uint32_t addr) {
    asm volatile("ldmatrix.sync.aligned.m8n8.x4.shared.b16 {%0,%1,%2,%3}, [%4];"
                 : "=r"(r[0]), "=r"(r[1]), "=r"(r[2]), "=r"(r[3]) : "r"(addr));
}
__device__ __forceinline__ void ldsm4t(uint32_t* r, uint32_t addr) {
    asm volatile("ldmatrix.sync.aligned.m8n8.x4.trans.shared.b16 {%0,%1,%2,%3}, [%4];"
                 : "=r"(r[0]), "=r"(r[1]), "=r"(r[2]), "=r"(r[3]) : "r"(addr));
}
__device__ __forceinline__ void mma_bf16(float* c, const uint32_t* a, const uint32_t* b) {
    asm volatile(
        "mma.sync.aligned.m16n8k16.row.col.f32.bf16.bf16.f32 "
        "{%0,%1,%2,%3}, {%4,%5,%6,%7}, {%8,%9}, {%0,%1,%2,%3};\n"
        : "+f"(c[0]), "+f"(c[1]), "+f"(c[2]), "+f"(c[3])
        : "r"(a[0]), "r"(a[1]), "r"(a[2]), "r"(a[3]), "r"(b[0]), "r"(b[1]));
}
__device__ __forceinline__ void mma_fp16(float* c, const uint32_t* a, const uint32_t* b) {
    asm volatile(
        "mma.sync.aligned.m16n8k16.row.col.f32.f16.f16.f32 "
        "{%0,%1,%2,%3}, {%4,%5,%6,%7}, {%8,%9}, {%0,%1,%2,%3};\n"
        : "+f"(c[0]), "+f"(c[1]), "+f"(c[2]), "+f"(c[3])
        : "r"(a[0]), "r"(a[1]), "r"(a[2]), "r"(a[3]), "r"(b[0]), "r"(b[1]));
}

// ---------------------------------------------------------------------------
// Tensor-core GEMM (unchanged from round 10 — known-good)
// ---------------------------------------------------------------------------
template<typename T, int NPASS>
__global__ __launch_bounds__(256, 2)
void gemm_tc(const T* __restrict__ Ahg, const T* __restrict__ Alg,
             const T* __restrict__ Bhg, const T* __restrict__ Blg,
             const float* __restrict__ bias,
             float* __restrict__ C, int K, int ldc)
{
    constexpr int APL  = (NPASS == 3) ? 2 : 1;
    constexpr int APB  = 10240;
    constexpr int BPB  = 10240;
    constexpr int BOFF = APL * APB;
    constexpr int STGB = APL * APB + 2 * BPB;

    extern __shared__ __align__(128) char smc[];
    const uint32_t sbase = (uint32_t)__cvta_generic_to_shared(smc);
    const int tid = threadIdx.x;
    const int warp = tid >> 5, lane = tid & 31;
    const int warp_m = warp >> 1, warp_n = warp & 1;
    const int g = lane >> 2, t = lane & 3;
    const int m0 = blockIdx.x << 7;
    const int n0 = blockIdx.y << 7;
    const int NCH = K >> 5;

    float acc[2][8][4];
#pragma unroll
    for (int i = 0; i < 2; ++i)
#pragma unroll
        for (int j = 0; j < 8; ++j)
#pragma unroll
            for (int r = 0; r < 4; ++r) acc[i][j][r] = 0.f;

    const int a_row = lane & 15;
    const int a_k16 = (lane >> 4) << 4;
    const int b_nt  = lane >> 4;
    const int b_row = lane & 7;
    const int b_k16 = ((lane >> 3) & 1) << 4;
    const uint32_t a_base = (uint32_t)((warp_m * 32 + a_row) * 80 + a_k16);
    const uint32_t b_base = (uint32_t)((warp_n * 64 + b_nt * 8 + b_row) * 80 + b_k16);

    auto loadSeg = [&](int chunk, int seg) {
        const uint32_t s = sbase + (uint32_t)(chunk & 1) * STGB;
        const int k0 = chunk << 5;
        int idx = tid + ((seg & 1) << 8);
        int r = idx >> 2, c = idx & 3;
        uint32_t so = (uint32_t)(r * 80 + c * 16);
        if (seg < 2) {
            size_t ga = (size_t)(m0 + r) * K + k0 + c * 8;
            cpa16(s + so, Ahg + ga);
            if (NPASS == 3) cpa16(s + APB + so, Alg + ga);
        } else {
            size_t gb = (size_t)(n0 + r) * K + k0 + c * 8;
            cpa16(s + BOFF + so, Bhg + gb);
            cpa16(s + BOFF + BPB + so, Blg + gb);
        }
    };

    auto compute = [&](int st, int lchunk, bool doLoad) {
        const uint32_t s = sbase + (uint32_t)st * STGB;
        int seg = 0;
#pragma unroll
        for (int ks = 0; ks < 2; ++ks) {
            const uint32_t ko = (uint32_t)(ks * 32);
            uint32_t ah[2][4], al[2][4];
#pragma unroll
            for (int i = 0; i < 2; ++i) {
                ldsm4(ah[i], s + a_base + (uint32_t)(i * 1280) + ko);
                if (NPASS == 3)
                    ldsm4(al[i], s + APB + a_base + (uint32_t)(i * 1280) + ko);
            }
#pragma unroll
            for (int jp = 0; jp < 4; ++jp) {
                uint32_t bh[4], bl[4];
                ldsm4(bh, s + BOFF + b_base + (uint32_t)(jp * 1280) + ko);
                ldsm4(bl, s + BOFF + BPB + b_base + (uint32_t)(jp * 1280) + ko);
#pragma unroll
                for (int i = 0; i < 2; ++i)
#pragma unroll
                    for (int jj = 0; jj < 2; ++jj) {
                        float* cc = acc[i][jp * 2 + jj];
                        if (NPASS == 3) {
                            mma_bf16(cc, ah[i], &bh[jj * 2]);
                            mma_bf16(cc, ah[i], &bl[jj * 2]);
                            mma_bf16(cc, al[i], &bh[jj * 2]);
                        } else {
                            mma_fp16(cc, ah[i], &bh[jj * 2]);
                            mma_fp16(cc, ah[i], &bl[jj * 2]);
                        }
                    }
                if (doLoad && seg < 4) { loadSeg(lchunk, seg); ++seg; }
            }
        }
    };

#pragma unroll
    for (int sgi = 0; sgi < 4; ++sgi) loadSeg(0, sgi);
    asm volatile("cp.async.commit_group;\n");

    for (int it = 0; it < NCH; ++it) {
        asm volatile("cp.async.wait_group 0;\n");
        __syncthreads();
        compute(it & 1, it + 1, (it + 1) < NCH);
        asm volatile("cp.async.commit_group;\n");
    }

#pragma unroll
    for (int i = 0; i < 2; ++i) {
        int row0 = m0 + warp_m * 32 + i * 16 + g;
#pragma unroll
        for (int j = 0; j < 8; ++j) {
            int col = n0 + warp_n * 64 + j * 8 + 2 * t;
            float b0 = bias ? bias[col] : 0.f;
            float b1 = bias ? bias[col + 1] : 0.f;
            float2 v0 = {acc[i][j][0] + b0, acc[i][j][1] + b1};
            float2 v1 = {acc[i][j][2] + b0, acc[i][j][3] + b1};
            *(float2*)&C[(size_t)row0 * ldc + col] = v0;
            *(float2*)&C[(size_t)(row0 + 8) * ldc + col] = v1;
        }
    }
}

// ---------------------------------------------------------------------------
// Tensor-core block-local attention.
// One CTA per (h, blk, b); 9 warps; rows/keys padded 129 -> 144.
// QK^T: bf16x3 (Q pre-scaled by 1/8). Softmax fp32 on fragments
// (padded cols masked -inf; normalization deferred to epilogue).
// PV: bf16x3 with P repacked C-frag -> A-frag, V via ldmatrix.trans.
// ---------------------------------------------------------------------------
#define MPAD   144
#define PITCH  72
#define PLANE_E (MPAD * PITCH)              // 10368 elems
#define ATT_SMEM (6 * PLANE_E * 2)          // 124416 B

__device__ __forceinline__ void store4_split(__nv_bfloat16* hp, __nv_bfloat16* lp,
                                             float4 v)
{
    __nv_bfloat16 h0 = __float2bfloat16(v.x), h1 = __float2bfloat16(v.y);
    __nv_bfloat16 h2 = __float2bfloat16(v.z), h3 = __float2bfloat16(v.w);
    *(__nv_bfloat162*)hp       = __nv_bfloat162(h0, h1);
    *(__nv_bfloat162*)(hp + 2) = __nv_bfloat162(h2, h3);
    *(__nv_bfloat162*)lp       = __nv_bfloat162(
        __float2bfloat16(v.x - __bfloat162float(h0)),
        __float2bfloat16(v.y - __bfloat162float(h1)));
    *(__nv_bfloat162*)(lp + 2) = __nv_bfloat162(
        __float2bfloat16(v.z - __bfloat162float(h2)),
        __float2bfloat16(v.w - __bfloat162float(h3)));
}

__device__ __forceinline__ void pack_hl(float a, float b, uint32_t& hi, uint32_t& lo)
{
    __nv_bfloat16 ha = __float2bfloat16(a), hb = __float2bfloat16(b);
    __nv_bfloat162 h(ha, hb);
    __nv_bfloat162 l(__float2bfloat16(a - __bfloat162float(ha)),
                     __float2bfloat16(b - __bfloat162float(hb)));
    hi = *(uint32_t*)&h;
    lo = *(uint32_t*)&l;
}

__global__ __launch_bounds__(288, 1)
void attn_local_tc()
{
    const int h = blockIdx.x, nb = blockIdx.y, b = blockIdx.z;
    const int tid = threadIdx.x, warp = tid >> 5, lane = tid & 31;
    extern __shared__ __align__(128) __nv_bfloat16 smb[];
    __nv_bfloat16* Qh = smb;
    __nv_bfloat16* Ql = Qh + PLANE_E;
    __nv_bfloat16* Kh = Ql + PLANE_E;
    __nv_bfloat16* Kl = Kh + PLANE_E;
    __nv_bfloat16* Vh = Kl + PLANE_E;
    __nv_bfloat16* Vl = Vh + PLANE_E;
    const uint32_t sb  = (uint32_t)__cvta_generic_to_shared(smb);
    const uint32_t uQh = sb;
    const uint32_t uQl = sb + 1 * PLANE_E * 2;
    const uint32_t uKh = sb + 2 * PLANE_E * 2;
    const uint32_t uKl = sb + 3 * PLANE_E * 2;
    const uint32_t uVh = sb + 4 * PLANE_E * 2;
    const uint32_t uVl = sb + 5 * PLANE_E * 2;

    const size_t base = ((size_t)(b * NTOK + nb * BLKT)) * QKVC + h * DK;

    // Load q/k/v rows, split into bf16 hi/lo, zero-pad rows 129..143.
    for (int s = tid; s < MPAD * 16; s += 288) {
        int r = s >> 4, c4 = (s & 15) << 2;
        float4 q = {0, 0, 0, 0}, k = q, v = q;
        if (r < BLKT) {
            q = *(const float4*)&g_qkv[base + (size_t)r * QKVC + c4];
            k = *(const float4*)&g_qkv[base + 1024 + (size_t)r * QKVC + c4];
            v = *(const float4*)&g_qkv[base + 2048 + (size_t)r * QKVC + c4];
            q.x *= 0.125f; q.y *= 0.125f; q.z *= 0.125f; q.w *= 0.125f;
        }
        int o = r * PITCH + c4;
        store4_split(Qh + o, Ql + o, q);
        store4_split(Kh + o, Kl + o, k);
        store4_split(Vh + o, Vl + o, v);
    }
    __syncthreads();

    const int g = lane >> 2, qt = lane & 3;

    // --- QK^T: warp = m16 tile (rows warp*16 .. +15) ---
    const uint32_t a_off = (uint32_t)(((warp * 16 + (lane & 15)) * PITCH +
                                      ((lane >> 4) << 3)) * 2);
    uint32_t aqh[4][4], aql[4][4];
#pragma unroll
    for (int kc = 0; kc < 4; ++kc) {
        ldsm4(aqh[kc], uQh + a_off + kc * 32);
        ldsm4(aql[kc], uQl + a_off + kc * 32);
    }

    float sc[18][4];
#pragma unroll
    for (int nt = 0; nt < 18; ++nt)
#pragma unroll
        for (int r = 0; r < 4; ++r) sc[nt][r] = 0.f;

    const uint32_t b_off = (uint32_t)((((lane >> 4) * 8 + (lane & 7)) * PITCH +
                                      (((lane >> 3) & 1) << 3)) * 2);
#pragma unroll
    for (int np = 0; np < 9; ++np) {
        const uint32_t ro = b_off + (uint32_t)(np * 16 * PITCH * 2);
#pragma unroll
        for (int kc = 0; kc < 4; ++kc) {
            uint32_t bh[4], bl[4];
            ldsm4(bh, uKh + ro + kc * 32);
            ldsm4(bl, uKl + ro + kc * 32);
            mma_bf16(sc[2 * np],     aqh[kc], &bh[0]);
            mma_bf16(sc[2 * np],     aqh[kc], &bl[0]);
            mma_bf16(sc[2 * np],     aql[kc], &bh[0]);
            mma_bf16(sc[2 * np + 1], aqh[kc], &bh[2]);
            mma_bf16(sc[2 * np + 1], aqh[kc], &bl[2]);
            mma_bf16(sc[2 * np + 1], aql[kc], &bh[2]);
        }
    }

    // --- softmax on fragments (rows g and g+8 of this warp's m16 tile) ---
    const float NINF = -CUDART_INF_F;
#pragma unroll
    for (int nt = 0; nt < 18; ++nt) {
        int c0 = nt * 8 + 2 * qt;
        if (c0 >= BLKT)     { sc[nt][0] = NINF; sc[nt][2] = NINF; }
        if (c0 + 1 >= BLKT) { sc[nt][1] = NINF; sc[nt][3] = NINF; }
    }
    float m0 = NINF, m1 = NINF;
#pragma unroll
    for (int nt = 0; nt < 18; ++nt) {
        m0 = fmaxf(m0, fmaxf(sc[nt][0], sc[nt][1]));
        m1 = fmaxf(m1, fmaxf(sc[nt][2], sc[nt][3]));
    }
    m0 = fmaxf(m0, __shfl_xor_sync(0xffffffffu, m0, 1));
    m0 = fmaxf(m0, __shfl_xor_sync(0xffffffffu, m0, 2));
    m1 = fmaxf(m1, __shfl_xor_sync(0xffffffffu, m1, 1));
    m1 = fmaxf(m1, __shfl_xor_sync(0xffffffffu, m1, 2));

    float s0 = 0.f, s1 = 0.f;
#pragma unroll
    for (int nt = 0; nt < 18; ++nt) {
        sc[nt][0] = __expf(sc[nt][0] - m0);
        sc[nt][1] = __expf(sc[nt][1] - m0);
        sc[nt][2] = __expf(sc[nt][2] - m1);
        sc[nt][3] = __expf(sc[nt][3] - m1);
        s0 += sc[nt][0] + sc[nt][1];
        s1 += sc[nt][2] + sc[nt][3];
    }
    s0 += __shfl_xor_sync(0xffffffffu, s0, 1);
    s0 += __shfl_xor_sync(0xffffffffu, s0, 2);
    s1 += __shfl_xor_sync(0xffffffffu, s1, 1);
    s1 += __shfl_xor_sync(0xffffffffu, s1, 2);
    const float inv0 = 1.f / s0, inv1 = 1.f / s1;

    // --- repack P fragments (C-frag -> A-frag), bf16 hi/lo ---
    uint32_t aph[9][4], apl[9][4];
#pragma unroll
    for (int kc = 0; kc < 9; ++kc) {
        pack_hl(sc[2 * kc][0],     sc[2 * kc][1],     aph[kc][0], apl[kc][0]);
        pack_hl(sc[2 * kc][2],     sc[2 * kc][3],     aph[kc][1], apl[kc][1]);
        pack_hl(sc[2 * kc + 1][0], sc[2 * kc + 1][1], aph[kc][2], apl[kc][2]);
        pack_hl(sc[2 * kc + 1][2], sc[2 * kc + 1][3], aph[kc][3], apl[kc][3]);
    }

    // --- PV: O[m16][64] ---
    float oc[8][4];
#pragma unroll
    for (int dt = 0; dt < 8; ++dt)
#pragma unroll
        for (int r = 0; r < 4; ++r) oc[dt][r] = 0.f;

    const uint32_t v_off = (uint32_t)(((((lane >> 3) & 1) * 8 + (lane & 7)) * PITCH +
                                      ((lane >> 4) << 3)) * 2);
#pragma unroll
    for (int kc = 0; kc < 9; ++kc) {
        const uint32_t ro = v_off + (uint32_t)(kc * 16 * PITCH * 2);
#pragma unroll
        for (int dp = 0; dp < 4; ++dp) {
            uint32_t vh[4], vl[4];
            ldsm4t(vh, uVh + ro + dp * 32);
            ldsm4t(vl, uVl + ro + dp * 32);
            mma_bf16(oc[2 * dp],     aph[kc], &vh[0]);
            mma_bf16(oc[2 * dp],     aph[kc], &vl[0]);
            mma_bf16(oc[2 * dp],     apl[kc], &vh[0]);
            mma_bf16(oc[2 * dp + 1], aph[kc], &vh[2]);
            mma_bf16(oc[2 * dp + 1], aph[kc], &vl[2]);
            mma_bf16(oc[2 * dp + 1], apl[kc], &vh[2]);
        }
    }

    // --- epilogue: normalize and store fp16 ---
    const int row0 = warp * 16 + g;
    const size_t obase = (size_t)(b * NTOK + nb * BLKT) * DMODEL + h * DK;
#pragma unroll
    for (int dt = 0; dt < 8; ++dt) {
        int col = dt * 8 + 2 * qt;
        if (row0 < BLKT)
            *(__half2*)&g_oh[obase + (size_t)row0 * DMODEL + col] =
                __floats2half2_rn(oc[dt][0] * inv0, oc[dt][1] * inv0);
        if (row0 + 8 < BLKT)
            *(__half2*)&g_oh[obase + (size_t)(row0 + 8) * DMODEL + col] =
                __floats2half2_rn(oc[dt][2] * inv1, oc[dt][3] * inv1);
    }
}

// ---------------------------------------------------------------------------
// Global (block-leader) attention: fp16 RMW on g_oh leader rows.
// ---------------------------------------------------------------------------
__global__ void attn_global()
{
    const int b = blockIdx.x >> 4, h = blockIdx.x & 15;
    const int lane = threadIdx.x;
    __shared__ float kg[32 * 65], vg[32 * 65], qg[32 * 65], pg[32 * 33];

    const size_t rb = ((size_t)(b * NTOK + lane * BLKT)) * QKVC + h * DK;
    for (int d = 0; d < 64; ++d) {
        qg[lane * 65 + d] = g_qkv[rb + d];
        kg[lane * 65 + d] = g_qkv[rb + 1024 + d];
        vg[lane * 65 + d] = g_qkv[rb + 2048 + d];
    }
    __syncwarp();

    for (int kk = 0; kk < 32; ++kk) {
        float a = 0.f;
        for (int d = 0; d < 64; ++d) a += qg[lane * 65 + d] * kg[kk * 65 + d];
        pg[lane * 33 + kk] = a * 0.125f;
    }
    float mx = -CUDART_INF_F;
    for (int kk = 0; kk < 32; ++kk) mx = fmaxf(mx, pg[lane * 33 + kk]);
    float sum = 0.f;
    for (int kk = 0; kk < 32; ++kk) {
        float e = __expf(pg[lane * 33 + kk] - mx);
        pg[lane * 33 + kk] = e;
        sum += e;
    }
    const float inv = 1.f / sum;
    __syncwarp();

    const size_t ob = ((size_t)(b * NTOK + lane * BLKT)) * DMODEL + h * DK;
    for (int d = 0; d < 64; ++d) {
        float acc = 0.f;
        for (int kk = 0; kk < 32; ++kk)
            acc += pg[lane * 33 + kk] * vg[kk * 65 + d];
        float cur = __half2float(g_oh[ob + d]);
        g_oh[ob + d] = __float2half(cur + acc * inv);
    }
}

// ---------------------------------------------------------------------------
extern "C" void kernel_launch(void* const* d_in, const int* in_sizes, int n_in,
                              void* d_out, int out_size)
{
    const float* x  = (const float*)d_in[0];
    const float* Wq = (const float*)d_in[1];
    const float* Wk = (const float*)d_in[2];
    const float* Wv = (const float*)d_in[3];
    const float* Wo = (const float*)d_in[4];
    const float* bo = (const float*)d_in[5];
    float* out = (float*)d_out;

    float* qkv = nullptr;
    __nv_bfloat16 *xh, *xl, *wh, *wl;
    __half *woh, *wol, *oh;
    cudaGetSymbolAddress((void**)&qkv, g_qkv);
    cudaGetSymbolAddress((void**)&xh, g_xh);
    cudaGetSymbolAddress((void**)&xl, g_xl);
    cudaGetSymbolAddress((void**)&wh, g_wh);
    cudaGetSymbolAddress((void**)&wl, g_wl);
    cudaGetSymbolAddress((void**)&woh, g_woh);
    cudaGetSymbolAddress((void**)&wol, g_wol);
    cudaGetSymbolAddress((void**)&oh, g_oh);

    // 0) precision splits
    split_bf16<<<(MROWS * DMODEL / 4 + 255) / 256, 256>>>(x, xh, xl, MROWS * DMODEL);
    split_w3<<<dim3(WN / 4 / 256, 3), 256>>>(Wq, Wk, Wv, wh, wl);
    split_fp16<<<(WN / 4 + 255) / 256, 256>>>(Wo, woh, wol, WN);

    // 1) QKV projection (bf16x3, TN=128, 2 CTAs/SM)
    constexpr int GS3 = 2 * (2 * 10240 + 2 * 10240);   // 81920
    constexpr int GS2 = 2 * (1 * 10240 + 2 * 10240);   // 61440
    auto* f3 = gemm_tc<__nv_bfloat16, 3>;
    auto* f2 = gemm_tc<__half, 2>;
    cudaFuncSetAttribute(f3, cudaFuncAttributeMaxDynamicSharedMemorySize, GS3);
    cudaFuncSetAttribute(f2, cudaFuncAttributeMaxDynamicSharedMemorySize, GS2);
    gemm_tc<__nv_bfloat16, 3><<<dim3(MROWS / 128, QKVC / 128), 256, GS3>>>(
        xh, xl, wh, wl, nullptr, qkv, DMODEL, QKVC);

    // 2) block-local attention (tensor cores) -> g_oh (fp16)
    cudaFuncSetAttribute(attn_local_tc,
                         cudaFuncAttributeMaxDynamicSharedMemorySize, ATT_SMEM);
    attn_local_tc<<<dim3(HEADS, NBLK, BATCH), 288, ATT_SMEM>>>();

    // 3) global leader attention (fp16 RMW into g_oh)
    attn_global<<<BATCH * HEADS, 32>>>();

    // 4) out = g_oh @ (Woh+Wol)^T + bo   (fp16 2-pass, TN=128, 2 CTAs/SM)
    gemm_tc<__half, 2><<<dim3(MROWS / 128, DMODEL / 128), 256, GS2>>>(
        oh, nullptr, woh, wol, bo, out, DMODEL, DMODEL);
}

// round 13
// speedup vs baseline: 3.9424x; 1.1957x over previous
#include <cuda_runtime.h>
#include <cuda_bf16.h>
#include <cuda_fp16.h>
#include <math_constants.h>
#include <cstdint>
#include <cstddef>

#define HEADS  16
#define DK     64
#define BLKT   129
#define NBLK   32
#define BATCH  4
#define NTOK   (BLKT * NBLK)        // 4128
#define MROWS  (BATCH * NTOK)       // 16512
#define DMODEL 1024
#define QKVC   3072
#define WN     (DMODEL * DMODEL)    // 1M

// Scratch (allocation-free rule: __device__ globals)
__device__ float g_qkv[(size_t)MROWS * QKVC];
__device__ __half g_xf[(size_t)MROWS * DMODEL];    // x rounded to fp16
__device__ __half g_wqh[(size_t)3 * WN];           // Wq|Wk|Wv fp16 hi
__device__ __half g_wql[(size_t)3 * WN];           // Wq|Wk|Wv fp16 lo
__device__ __half g_woh[(size_t)WN];
__device__ __half g_wol[(size_t)WN];
__device__ __half g_oh[(size_t)MROWS * DMODEL];    // attention output (fp16)

// ---------------------------------------------------------------------------
// Split kernels
// ---------------------------------------------------------------------------
__global__ void round_x16(const float* __restrict__ in, __half* __restrict__ out, int n)
{
    int i = (blockIdx.x * blockDim.x + threadIdx.x) * 4;
    if (i >= n) return;
    float4 v = *(const float4*)(in + i);
    *(__half2*)(out + i)     = __half2(__float2half(v.x), __float2half(v.y));
    *(__half2*)(out + i + 2) = __half2(__float2half(v.z), __float2half(v.w));
}

// fused Wq/Wk/Wv fp16 hi/lo split (blockIdx.y selects weight)
__global__ void split_w3_16(const float* __restrict__ Wq, const float* __restrict__ Wk,
                            const float* __restrict__ Wv,
                            __half* __restrict__ hi, __half* __restrict__ lo)
{
    const int w = blockIdx.y;
    const float* src = (w == 0) ? Wq : (w == 1) ? Wk : Wv;
    size_t off = (size_t)w * WN;
    int i = (blockIdx.x * blockDim.x + threadIdx.x) * 4;
    if (i >= WN) return;
    float4 v = *(const float4*)(src + i);
    __half h0 = __float2half(v.x), h1 = __float2half(v.y);
    __half h2 = __float2half(v.z), h3 = __float2half(v.w);
    *(__half2*)(hi + off + i)     = __half2(h0, h1);
    *(__half2*)(hi + off + i + 2) = __half2(h2, h3);
    *(__half2*)(lo + off + i) = __half2(__float2half(v.x - __half2float(h0)),
                                        __float2half(v.y - __half2float(h1)));
    *(__half2*)(lo + off + i + 2) = __half2(__float2half(v.z - __half2float(h2)),
                                            __float2half(v.w - __half2float(h3)));
}

__global__ void split_fp16(const float* __restrict__ in,
                           __half* __restrict__ hi, __half* __restrict__ lo, int n)
{
    int i = (blockIdx.x * blockDim.x + threadIdx.x) * 4;
    if (i >= n) return;
    float4 v = *(const float4*)(in + i);
    __half h0 = __float2half(v.x), h1 = __float2half(v.y);
    __half h2 = __float2half(v.z), h3 = __float2half(v.w);
    *(__half2*)(hi + i)     = __half2(h0, h1);
    *(__half2*)(hi + i + 2) = __half2(h2, h3);
    *(__half2*)(lo + i) = __half2(__float2half(v.x - __half2float(h0)),
                                  __float2half(v.y - __half2float(h1)));
    *(__half2*)(lo + i + 2) = __half2(__float2half(v.z - __half2float(h2)),
                                      __float2half(v.w - __half2float(h3)));
}

// ---------------------------------------------------------------------------
// MMA / ldmatrix helpers
// ---------------------------------------------------------------------------
__device__ __forceinline__ void cpa16(uint32_t dst, const void* src) {
    asm volatile("cp.async.cg.shared.global [%0], [%1], 16;\n" :: "r"(dst), "l"(src));
}
__device__ __forceinline__ void ldsm4(uint32_t* r, uint32_t addr) {
    asm volatile("ldmatrix.sync.aligned.m8n8.x4.shared.b16 {%0,%1,%2,%3}, [%4];"
                 : "=r"(r[0]), "=r"(r[1]), "=r"(r[2]), "=r"(r[3]) : "r"(addr));
}
__device__ __forceinline__ void ldsm4t(uint32_t* r, uint32_t addr) {
    asm volatile("ldmatrix.sync.aligned.m8n8.x4.trans.shared.b16 {%0,%1,%2,%3}, [%4];"
                 : "=r"(r[0]), "=r"(r[1]), "=r"(r[2]), "=r"(r[3]) : "r"(addr));
}
__device__ __forceinline__ void mma_bf16(float* c, const uint32_t* a, const uint32_t* b) {
    asm volatile(
        "mma.sync.aligned.m16n8k16.row.col.f32.bf16.bf16.f32 "
        "{%0,%1,%2,%3}, {%4,%5,%6,%7}, {%8,%9}, {%0,%1,%2,%3};\n"
        : "+f"(c[0]), "+f"(c[1]), "+f"(c[2]), "+f"(c[3])
        : "r"(a[0]), "r"(a[1]), "r"(a[2]), "r"(a[3]), "r"(b[0]), "r"(b[1]));
}
__device__ __forceinline__ void mma_fp16(float* c, const uint32_t* a, const uint32_t* b) {
    asm volatile(
        "mma.sync.aligned.m16n8k16.row.col.f32.f16.f16.f32 "
        "{%0,%1,%2,%3}, {%4,%5,%6,%7}, {%8,%9}, {%0,%1,%2,%3};\n"
        : "+f"(c[0]), "+f"(c[1]), "+f"(c[2]), "+f"(c[3])
        : "r"(a[0]), "r"(a[1]), "r"(a[2]), "r"(a[3]), "r"(b[0]), "r"(b[1]));
}

// ---------------------------------------------------------------------------
// Tensor-core GEMM (NT), fp16 2-pass: C = A * (Bh + Bl)^T  (+bias)
// TM=128, TN=128, BK=32, 8 warps (4m x 2n), 2-stage cp.async, 2 CTAs/SM.
// ---------------------------------------------------------------------------
__global__ __launch_bounds__(256, 2)
void gemm_f16p2(const __half* __restrict__ Ag,
                const __half* __restrict__ Bhg, const __half* __restrict__ Blg,
                const float* __restrict__ bias,
                float* __restrict__ C, int K, int ldc)
{
    constexpr int APB  = 10240;
    constexpr int BPB  = 10240;
    constexpr int BOFF = APB;
    constexpr int STGB = APB + 2 * BPB;        // 30720

    extern __shared__ __align__(128) char smc[];
    const uint32_t sbase = (uint32_t)__cvta_generic_to_shared(smc);
    const int tid = threadIdx.x;
    const int warp = tid >> 5, lane = tid & 31;
    const int warp_m = warp >> 1, warp_n = warp & 1;
    const int g = lane >> 2, t = lane & 3;
    const int m0 = blockIdx.x << 7;
    const int n0 = blockIdx.y << 7;
    const int NCH = K >> 5;

    float acc[2][8][4];
#pragma unroll
    for (int i = 0; i < 2; ++i)
#pragma unroll
        for (int j = 0; j < 8; ++j)
#pragma unroll
            for (int r = 0; r < 4; ++r) acc[i][j][r] = 0.f;

    const int a_row = lane & 15;
    const int a_k16 = (lane >> 4) << 4;
    const uint32_t a_base = (uint32_t)((warp_m * 32 + a_row) * 80 + a_k16);
    const uint32_t b_base = (uint32_t)((warp_n * 64 + (lane >> 4) * 8 + (lane & 7)) * 80 +
                                       (((lane >> 3) & 1) << 4));

    auto loadSeg = [&](int chunk, int seg) {
        const uint32_t s = sbase + (uint32_t)(chunk & 1) * STGB;
        const int k0 = chunk << 5;
        int idx = tid + ((seg & 1) << 8);
        int r = idx >> 2, c = idx & 3;
        uint32_t so = (uint32_t)(r * 80 + c * 16);
        if (seg < 2) {
            size_t ga = (size_t)(m0 + r) * K + k0 + c * 8;
            cpa16(s + so, Ag + ga);
        } else {
            size_t gb = (size_t)(n0 + r) * K + k0 + c * 8;
            cpa16(s + BOFF + so, Bhg + gb);
            cpa16(s + BOFF + BPB + so, Blg + gb);
        }
    };

    auto compute = [&](int st, int lchunk, bool doLoad) {
        const uint32_t s = sbase + (uint32_t)st * STGB;
        int seg = 0;
#pragma unroll
        for (int ks = 0; ks < 2; ++ks) {
            const uint32_t ko = (uint32_t)(ks * 32);
            uint32_t ah[2][4];
#pragma unroll
            for (int i = 0; i < 2; ++i)
                ldsm4(ah[i], s + a_base + (uint32_t)(i * 1280) + ko);
#pragma unroll
            for (int jp = 0; jp < 4; ++jp) {
                uint32_t bh[4], bl[4];
                ldsm4(bh, s + BOFF + b_base + (uint32_t)(jp * 1280) + ko);
                ldsm4(bl, s + BOFF + BPB + b_base + (uint32_t)(jp * 1280) + ko);
#pragma unroll
                for (int i = 0; i < 2; ++i)
#pragma unroll
                    for (int jj = 0; jj < 2; ++jj) {
                        float* cc = acc[i][jp * 2 + jj];
                        mma_fp16(cc, ah[i], &bh[jj * 2]);
                        mma_fp16(cc, ah[i], &bl[jj * 2]);
                    }
                if (doLoad && seg < 4) { loadSeg(lchunk, seg); ++seg; }
            }
        }
    };

#pragma unroll
    for (int sgi = 0; sgi < 4; ++sgi) loadSeg(0, sgi);
    asm volatile("cp.async.commit_group;\n");

    for (int it = 0; it < NCH; ++it) {
        asm volatile("cp.async.wait_group 0;\n");
        __syncthreads();
        compute(it & 1, it + 1, (it + 1) < NCH);
        asm volatile("cp.async.commit_group;\n");
    }

#pragma unroll
    for (int i = 0; i < 2; ++i) {
        int row0 = m0 + warp_m * 32 + i * 16 + g;
#pragma unroll
        for (int j = 0; j < 8; ++j) {
            int col = n0 + warp_n * 64 + j * 8 + 2 * t;
            float b0 = bias ? bias[col] : 0.f;
            float b1 = bias ? bias[col + 1] : 0.f;
            float2 v0 = {acc[i][j][0] + b0, acc[i][j][1] + b1};
            float2 v1 = {acc[i][j][2] + b0, acc[i][j][3] + b1};
            *(float2*)&C[(size_t)row0 * ldc + col] = v0;
            *(float2*)&C[(size_t)(row0 + 8) * ldc + col] = v1;
        }
    }
}

// ---------------------------------------------------------------------------
// Tensor-core block-local attention (known-good).
// ---------------------------------------------------------------------------
#define MPAD   144
#define PITCH  72
#define PLANE_E (MPAD * PITCH)              // 10368 elems
#define ATT_SMEM (6 * PLANE_E * 2)          // 124416 B

__device__ __forceinline__ void store4_split(__nv_bfloat16* hp, __nv_bfloat16* lp,
                                             float4 v)
{
    __nv_bfloat16 h0 = __float2bfloat16(v.x), h1 = __float2bfloat16(v.y);
    __nv_bfloat16 h2 = __float2bfloat16(v.z), h3 = __float2bfloat16(v.w);
    *(__nv_bfloat162*)hp       = __nv_bfloat162(h0, h1);
    *(__nv_bfloat162*)(hp + 2) = __nv_bfloat162(h2, h3);
    *(__nv_bfloat162*)lp       = __nv_bfloat162(
        __float2bfloat16(v.x - __bfloat162float(h0)),
        __float2bfloat16(v.y - __bfloat162float(h1)));
    *(__nv_bfloat162*)(lp + 2) = __nv_bfloat162(
        __float2bfloat16(v.z - __bfloat162float(h2)),
        __float2bfloat16(v.w - __bfloat162float(h3)));
}

__device__ __forceinline__ void pack_hl(float a, float b, uint32_t& hi, uint32_t& lo)
{
    __nv_bfloat16 ha = __float2bfloat16(a), hb = __float2bfloat16(b);
    __nv_bfloat162 h(ha, hb);
    __nv_bfloat162 l(__float2bfloat16(a - __bfloat162float(ha)),
                     __float2bfloat16(b - __bfloat162float(hb)));
    hi = *(uint32_t*)&h;
    lo = *(uint32_t*)&l;
}

__global__ __launch_bounds__(288, 1)
void attn_local_tc()
{
    const int h = blockIdx.x, nb = blockIdx.y, b = blockIdx.z;
    const int tid = threadIdx.x, warp = tid >> 5, lane = tid & 31;
    extern __shared__ __align__(128) __nv_bfloat16 smb[];
    __nv_bfloat16* Qh = smb;
    __nv_bfloat16* Ql = Qh + PLANE_E;
    __nv_bfloat16* Kh = Ql + PLANE_E;
    __nv_bfloat16* Kl = Kh + PLANE_E;
    __nv_bfloat16* Vh = Kl + PLANE_E;
    __nv_bfloat16* Vl = Vh + PLANE_E;
    const uint32_t sb  = (uint32_t)__cvta_generic_to_shared(smb);
    const uint32_t uQh = sb;
    const uint32_t uQl = sb + 1 * PLANE_E * 2;
    const uint32_t uKh = sb + 2 * PLANE_E * 2;
    const uint32_t uKl = sb + 3 * PLANE_E * 2;
    const uint32_t uVh = sb + 4 * PLANE_E * 2;
    const uint32_t uVl = sb + 5 * PLANE_E * 2;

    const size_t base = ((size_t)(b * NTOK + nb * BLKT)) * QKVC + h * DK;

    for (int s = tid; s < MPAD * 16; s += 288) {
        int r = s >> 4, c4 = (s & 15) << 2;
        float4 q = {0, 0, 0, 0}, k = q, v = q;
        if (r < BLKT) {
            q = *(const float4*)&g_qkv[base + (size_t)r * QKVC + c4];
            k = *(const float4*)&g_qkv[base + 1024 + (size_t)r * QKVC + c4];
            v = *(const float4*)&g_qkv[base + 2048 + (size_t)r * QKVC + c4];
            q.x *= 0.125f; q.y *= 0.125f; q.z *= 0.125f; q.w *= 0.125f;
        }
        int o = r * PITCH + c4;
        store4_split(Qh + o, Ql + o, q);
        store4_split(Kh + o, Kl + o, k);
        store4_split(Vh + o, Vl + o, v);
    }
    __syncthreads();

    const int g = lane >> 2, qt = lane & 3;

    const uint32_t a_off = (uint32_t)(((warp * 16 + (lane & 15)) * PITCH +
                                      ((lane >> 4) << 3)) * 2);
    uint32_t aqh[4][4], aql[4][4];
#pragma unroll
    for (int kc = 0; kc < 4; ++kc) {
        ldsm4(aqh[kc], uQh + a_off + kc * 32);
        ldsm4(aql[kc], uQl + a_off + kc * 32);
    }

    float sc[18][4];
#pragma unroll
    for (int nt = 0; nt < 18; ++nt)
#pragma unroll
        for (int r = 0; r < 4; ++r) sc[nt][r] = 0.f;

    const uint32_t b_off = (uint32_t)((((lane >> 4) * 8 + (lane & 7)) * PITCH +
                                      (((lane >> 3) & 1) << 3)) * 2);
#pragma unroll
    for (int np = 0; np < 9; ++np) {
        const uint32_t ro = b_off + (uint32_t)(np * 16 * PITCH * 2);
#pragma unroll
        for (int kc = 0; kc < 4; ++kc) {
            uint32_t bh[4], bl[4];
            ldsm4(bh, uKh + ro + kc * 32);
            ldsm4(bl, uKl + ro + kc * 32);
            mma_bf16(sc[2 * np],     aqh[kc], &bh[0]);
            mma_bf16(sc[2 * np],     aqh[kc], &bl[0]);
            mma_bf16(sc[2 * np],     aql[kc], &bh[0]);
            mma_bf16(sc[2 * np + 1], aqh[kc], &bh[2]);
            mma_bf16(sc[2 * np + 1], aqh[kc], &bl[2]);
            mma_bf16(sc[2 * np + 1], aql[kc], &bh[2]);
        }
    }

    const float NINF = -CUDART_INF_F;
#pragma unroll
    for (int nt = 0; nt < 18; ++nt) {
        int c0 = nt * 8 + 2 * qt;
        if (c0 >= BLKT)     { sc[nt][0] = NINF; sc[nt][2] = NINF; }
        if (c0 + 1 >= BLKT) { sc[nt][1] = NINF; sc[nt][3] = NINF; }
    }
    float m0 = NINF, m1 = NINF;
#pragma unroll
    for (int nt = 0; nt < 18; ++nt) {
        m0 = fmaxf(m0, fmaxf(sc[nt][0], sc[nt][1]));
        m1 = fmaxf(m1, fmaxf(sc[nt][2], sc[nt][3]));
    }
    m0 = fmaxf(m0, __shfl_xor_sync(0xffffffffu, m0, 1));
    m0 = fmaxf(m0, __shfl_xor_sync(0xffffffffu, m0, 2));
    m1 = fmaxf(m1, __shfl_xor_sync(0xffffffffu, m1, 1));
    m1 = fmaxf(m1, __shfl_xor_sync(0xffffffffu, m1, 2));

    float s0 = 0.f, s1 = 0.f;
#pragma unroll
    for (int nt = 0; nt < 18; ++nt) {
        sc[nt][0] = __expf(sc[nt][0] - m0);
        sc[nt][1] = __expf(sc[nt][1] - m0);
        sc[nt][2] = __expf(sc[nt][2] - m1);
        sc[nt][3] = __expf(sc[nt][3] - m1);
        s0 += sc[nt][0] + sc[nt][1];
        s1 += sc[nt][2] + sc[nt][3];
    }
    s0 += __shfl_xor_sync(0xffffffffu, s0, 1);
    s0 += __shfl_xor_sync(0xffffffffu, s0, 2);
    s1 += __shfl_xor_sync(0xffffffffu, s1, 1);
    s1 += __shfl_xor_sync(0xffffffffu, s1, 2);
    const float inv0 = 1.f / s0, inv1 = 1.f / s1;

    uint32_t aph[9][4], apl[9][4];
#pragma unroll
    for (int kc = 0; kc < 9; ++kc) {
        pack_hl(sc[2 * kc][0],     sc[2 * kc][1],     aph[kc][0], apl[kc][0]);
        pack_hl(sc[2 * kc][2],     sc[2 * kc][3],     aph[kc][1], apl[kc][1]);
        pack_hl(sc[2 * kc + 1][0], sc[2 * kc + 1][1], aph[kc][2], apl[kc][2]);
        pack_hl(sc[2 * kc + 1][2], sc[2 * kc + 1][3], aph[kc][3], apl[kc][3]);
    }

    float oc[8][4];
#pragma unroll
    for (int dt = 0; dt < 8; ++dt)
#pragma unroll
        for (int r = 0; r < 4; ++r) oc[dt][r] = 0.f;

    const uint32_t v_off = (uint32_t)(((((lane >> 3) & 1) * 8 + (lane & 7)) * PITCH +
                                      ((lane >> 4) << 3)) * 2);
#pragma unroll
    for (int kc = 0; kc < 9; ++kc) {
        const uint32_t ro = v_off + (uint32_t)(kc * 16 * PITCH * 2);
#pragma unroll
        for (int dp = 0; dp < 4; ++dp) {
            uint32_t vh[4], vl[4];
            ldsm4t(vh, uVh + ro + dp * 32);
            ldsm4t(vl, uVl + ro + dp * 32);
            mma_bf16(oc[2 * dp],     aph[kc], &vh[0]);
            mma_bf16(oc[2 * dp],     aph[kc], &vl[0]);
            mma_bf16(oc[2 * dp],     apl[kc], &vh[0]);
            mma_bf16(oc[2 * dp + 1], aph[kc], &vh[2]);
            mma_bf16(oc[2 * dp + 1], aph[kc], &vl[2]);
            mma_bf16(oc[2 * dp + 1], apl[kc], &vh[2]);
        }
    }

    const int row0 = warp * 16 + g;
    const size_t obase = (size_t)(b * NTOK + nb * BLKT) * DMODEL + h * DK;
#pragma unroll
    for (int dt = 0; dt < 8; ++dt) {
        int col = dt * 8 + 2 * qt;
        if (row0 < BLKT)
            *(__half2*)&g_oh[obase + (size_t)row0 * DMODEL + col] =
                __floats2half2_rn(oc[dt][0] * inv0, oc[dt][1] * inv0);
        if (row0 + 8 < BLKT)
            *(__half2*)&g_oh[obase + (size_t)(row0 + 8) * DMODEL + col] =
                __floats2half2_rn(oc[dt][2] * inv1, oc[dt][3] * inv1);
    }
}

// ---------------------------------------------------------------------------
// Global (block-leader) attention: fp16 RMW on g_oh leader rows.
// ---------------------------------------------------------------------------
__global__ void attn_global()
{
    const int b = blockIdx.x >> 4, h = blockIdx.x & 15;
    const int lane = threadIdx.x;
    __shared__ float kg[32 * 65], vg[32 * 65], qg[32 * 65], pg[32 * 33];

    const size_t rb = ((size_t)(b * NTOK + lane * BLKT)) * QKVC + h * DK;
    for (int d = 0; d < 64; ++d) {
        qg[lane * 65 + d] = g_qkv[rb + d];
        kg[lane * 65 + d] = g_qkv[rb + 1024 + d];
        vg[lane * 65 + d] = g_qkv[rb + 2048 + d];
    }
    __syncwarp();

    for (int kk = 0; kk < 32; ++kk) {
        float a = 0.f;
        for (int d = 0; d < 64; ++d) a += qg[lane * 65 + d] * kg[kk * 65 + d];
        pg[lane * 33 + kk] = a * 0.125f;
    }
    float mx = -CUDART_INF_F;
    for (int kk = 0; kk < 32; ++kk) mx = fmaxf(mx, pg[lane * 33 + kk]);
    float sum = 0.f;
    for (int kk = 0; kk < 32; ++kk) {
        float e = __expf(pg[lane * 33 + kk] - mx);
        pg[lane * 33 + kk] = e;
        sum += e;
    }
    const float inv = 1.f / sum;
    __syncwarp();

    const size_t ob = ((size_t)(b * NTOK + lane * BLKT)) * DMODEL + h * DK;
    for (int d = 0; d < 64; ++d) {
        float acc = 0.f;
        for (int kk = 0; kk < 32; ++kk)
            acc += pg[lane * 33 + kk] * vg[kk * 65 + d];
        float cur = __half2float(g_oh[ob + d]);
        g_oh[ob + d] = __float2half(cur + acc * inv);
    }
}

// ---------------------------------------------------------------------------
extern "C" void kernel_launch(void* const* d_in, const int* in_sizes, int n_in,
                              void* d_out, int out_size)
{
    const float* x  = (const float*)d_in[0];
    const float* Wq = (const float*)d_in[1];
    const float* Wk = (const float*)d_in[2];
    const float* Wv = (const float*)d_in[3];
    const float* Wo = (const float*)d_in[4];
    const float* bo = (const float*)d_in[5];
    float* out = (float*)d_out;

    float* qkv = nullptr;
    __half *xf, *wqh, *wql, *woh, *wol, *oh;
    cudaGetSymbolAddress((void**)&qkv, g_qkv);
    cudaGetSymbolAddress((void**)&xf, g_xf);
    cudaGetSymbolAddress((void**)&wqh, g_wqh);
    cudaGetSymbolAddress((void**)&wql, g_wql);
    cudaGetSymbolAddress((void**)&woh, g_woh);
    cudaGetSymbolAddress((void**)&wol, g_wol);
    cudaGetSymbolAddress((void**)&oh, g_oh);

    // 0) precision prep
    round_x16<<<(MROWS * DMODEL / 4 + 255) / 256, 256>>>(x, xf, MROWS * DMODEL);
    split_w3_16<<<dim3(WN / 4 / 256, 3), 256>>>(Wq, Wk, Wv, wqh, wql);
    split_fp16<<<(WN / 4 + 255) / 256, 256>>>(Wo, woh, wol, WN);

    // 1) QKV projection (fp16 2-pass, TN=128, 2 CTAs/SM)
    constexpr int GS2 = 2 * (10240 + 2 * 10240);   // 61440
    cudaFuncSetAttribute(gemm_f16p2, cudaFuncAttributeMaxDynamicSharedMemorySize, GS2);
    gemm_f16p2<<<dim3(MROWS / 128, QKVC / 128), 256, GS2>>>(
        xf, wqh, wql, nullptr, qkv, DMODEL, QKVC);

    // 2) block-local attention (tensor cores) -> g_oh (fp16)
    cudaFuncSetAttribute(attn_local_tc,
                         cudaFuncAttributeMaxDynamicSharedMemorySize, ATT_SMEM);
    attn_local_tc<<<dim3(HEADS, NBLK, BATCH), 288, ATT_SMEM>>>();

    // 3) global leader attention (fp16 RMW into g_oh)
    attn_global<<<BATCH * HEADS, 32>>>();

    // 4) out = g_oh @ (Woh+Wol)^T + bo   (fp16 2-pass)
    gemm_f16p2<<<dim3(MROWS / 128, DMODEL / 128), 256, GS2>>>(
        oh, woh, wol, bo, out, DMODEL, DMODEL);
}